// round 11
// baseline (speedup 1.0000x reference)
#include <cuda_runtime.h>
#include <cuda_bf16.h>

#define B_ 2
#define S_ 2048
#define E_ 1024
#define H_ 16
#define D_ 64
#define M_ 4096
#define K_ 1024

// ---------------------------------------------------------------------------
// Scratch (__device__ globals). All bf16 hi/lo pairs.
// ---------------------------------------------------------------------------
__device__ __align__(256) __nv_bfloat16 g_xh[(size_t)3*M_*K_];  // split q/k/v inputs
__device__ __align__(256) __nv_bfloat16 g_xl[(size_t)3*M_*K_];
__device__ __align__(256) __nv_bfloat16 g_wh[(size_t)4*K_*K_];  // qkvw(3M) + projw(1M)
__device__ __align__(256) __nv_bfloat16 g_wl[(size_t)4*K_*K_];
__device__ __align__(256) __nv_bfloat16 g_sh[(size_t)3*B_*H_*S_*D_]; // split q/k/v heads
__device__ __align__(256) __nv_bfloat16 g_sl[(size_t)3*B_*H_*S_*D_];
__device__ __align__(256) __nv_bfloat16 g_ch[(size_t)M_*E_];    // split ctx
__device__ __align__(256) __nv_bfloat16 g_cl[(size_t)M_*E_];

// ---------------------------------------------------------------------------
// Helpers
// ---------------------------------------------------------------------------
__device__ __forceinline__ unsigned cvta_s(const void* p) {
    return (unsigned)__cvta_generic_to_shared(p);
}
__device__ __forceinline__ unsigned pk2(__nv_bfloat16 a, __nv_bfloat16 b) {
    return (unsigned)__bfloat16_as_ushort(a) | ((unsigned)__bfloat16_as_ushort(b) << 16);
}
__device__ __forceinline__ void splitpk(float x, float y, unsigned& h, unsigned& l) {
    __nv_bfloat16 hx = __float2bfloat16_rn(x);
    __nv_bfloat16 hy = __float2bfloat16_rn(y);
    float rx = x - __bfloat162float(hx);
    float ry = y - __bfloat162float(hy);
    h = pk2(hx, hy);
    l = pk2(__float2bfloat16_rn(rx), __float2bfloat16_rn(ry));
}
__device__ __forceinline__ void ldsm4(unsigned& r0, unsigned& r1, unsigned& r2, unsigned& r3,
                                      unsigned a) {
    asm volatile("ldmatrix.sync.aligned.m8n8.x4.shared.b16 {%0,%1,%2,%3}, [%4];"
                 : "=r"(r0), "=r"(r1), "=r"(r2), "=r"(r3) : "r"(a));
}
__device__ __forceinline__ void ldsm4t(unsigned& r0, unsigned& r1, unsigned& r2, unsigned& r3,
                                       unsigned a) {
    asm volatile("ldmatrix.sync.aligned.m8n8.x4.trans.shared.b16 {%0,%1,%2,%3}, [%4];"
                 : "=r"(r0), "=r"(r1), "=r"(r2), "=r"(r3) : "r"(a));
}
// NON-volatile: pure register op; lets ptxas interleave independent MMAs.
__device__ __forceinline__ void mma16816(float* c,
                                         unsigned a0, unsigned a1, unsigned a2, unsigned a3,
                                         unsigned b0, unsigned b1) {
    asm("mma.sync.aligned.m16n8k16.row.col.f32.bf16.bf16.f32 "
        "{%0,%1,%2,%3}, {%4,%5,%6,%7}, {%8,%9}, {%0,%1,%2,%3};"
        : "+f"(c[0]), "+f"(c[1]), "+f"(c[2]), "+f"(c[3])
        : "r"(a0), "r"(a1), "r"(a2), "r"(a3), "r"(b0), "r"(b1));
}
__device__ __forceinline__ void cpa16(unsigned dst, const void* src) {
    asm volatile("cp.async.cg.shared.global [%0], [%1], 16;" :: "r"(dst), "l"(src));
}
__device__ __forceinline__ void cpa_commit() {
    asm volatile("cp.async.commit_group;" ::: "memory");
}
template<int N>
__device__ __forceinline__ void cpa_wait() {
    asm volatile("cp.async.wait_group %0;" :: "n"(N) : "memory");
}

// ---------------------------------------------------------------------------
// Split pass: fp32 -> bf16 hi/lo for q/k/v inputs + qkv weight + proj weight.
// ---------------------------------------------------------------------------
__global__ void __launch_bounds__(256) split_all(
    const float* __restrict__ q, const float* __restrict__ k, const float* __restrict__ v,
    const float* __restrict__ qkvw, const float* __restrict__ projw)
{
    size_t i4 = (size_t)blockIdx.x * 256 + threadIdx.x;
    const size_t XQ = (size_t)M_ * K_ / 4;
    const size_t WQ = (size_t)3 * K_ * K_ / 4;
    const float* src; __nv_bfloat16 *dh, *dl; size_t o;
    if (i4 < 3 * XQ) {
        size_t sel = i4 / XQ; o = i4 - sel * XQ;
        src = (sel == 0) ? q : ((sel == 1) ? k : v);
        dh = g_xh + sel * (size_t)M_ * K_;
        dl = g_xl + sel * (size_t)M_ * K_;
    } else if (i4 < 3 * XQ + WQ) {
        o = i4 - 3 * XQ; src = qkvw; dh = g_wh; dl = g_wl;
    } else {
        o = i4 - 3 * XQ - WQ; src = projw;
        dh = g_wh + (size_t)3 * K_ * K_;
        dl = g_wl + (size_t)3 * K_ * K_;
    }
    float4 x = *((const float4*)src + o);
    unsigned h0, l0, h1, l1;
    splitpk(x.x, x.y, h0, l0);
    splitpk(x.z, x.w, h1, l1);
    *(uint2*)(dh + o * 4) = make_uint2(h0, h1);
    *(uint2*)(dl + o * 4) = make_uint2(l0, l1);
}

// ---------------------------------------------------------------------------
// bf16x3 GEMM on pre-split inputs. CTA 128m x 64n, 8 warps, warp tile 32x32.
// K-chunk 64, cp.async double buffered: 110592 B total -> 2 CTAs/SM.
// R11: MMA loop restructured into 3 passes (hh / hl / lh) so same-acc MMAs
// are 8 apart; mma asm non-volatile.
// ---------------------------------------------------------------------------
#define GEMM_BUF  55296
#define GEMM_SMEM (2 * GEMM_BUF)

template<int QKV>
__global__ void __launch_bounds__(256, 2) gemm_bf16(
    const __nv_bfloat16* __restrict__ Ah0, const __nv_bfloat16* __restrict__ Al0,
    const __nv_bfloat16* __restrict__ Wh, const __nv_bfloat16* __restrict__ Wl,
    const float* __restrict__ bias, float* __restrict__ out)
{
    extern __shared__ __align__(1024) __nv_bfloat16 smg[];
    const unsigned sb = cvta_s(smg);

    const int tid = threadIdx.x, lane = tid & 31, wid = tid >> 5;
    const int wm = wid & 3, wn = wid >> 2;
    const int m0 = blockIdx.y * 128, n0 = blockIdx.x * 64;

    const __nv_bfloat16* Ah = Ah0;
    const __nv_bfloat16* Al = Al0;
    int sel = 0;
    if (QKV) {
        sel = n0 >> 10;
        Ah += (size_t)sel * M_ * K_;
        Al += (size_t)sel * M_ * K_;
    }

    int ar[4], as_[4], asg[4];
    #pragma unroll
    for (int i = 0; i < 4; i++) {
        int idx = tid + 256 * i;
        ar[i] = idx >> 3;
        asg[i] = (idx & 7) * 8;
        as_[i] = (idx >> 3) * 144 + (idx & 7) * 16;
    }
    int br[2], bs_[2], bsg[2];
    #pragma unroll
    for (int i = 0; i < 2; i++) {
        int idx = tid + 256 * i;
        br[i] = idx >> 3;
        bsg[i] = (idx & 7) * 8;
        bs_[i] = (idx >> 3) * 144 + (idx & 7) * 16;
    }

    #pragma unroll
    for (int i = 0; i < 4; i++) {
        unsigned d = sb + as_[i];
        size_t g = (size_t)(m0 + ar[i]) * K_ + asg[i];
        cpa16(d,         Ah + g);
        cpa16(d + 18432, Al + g);
    }
    #pragma unroll
    for (int i = 0; i < 2; i++) {
        unsigned d = sb + 36864 + bs_[i];
        size_t g = (size_t)(n0 + br[i]) * K_ + bsg[i];
        cpa16(d,        Wh + g);
        cpa16(d + 9216, Wl + g);
    }
    cpa_commit();

    float acc[2][4][4];
    #pragma unroll
    for (int mi = 0; mi < 2; mi++)
        #pragma unroll
        for (int nt = 0; nt < 4; nt++)
            #pragma unroll
            for (int q = 0; q < 4; q++) acc[mi][nt][q] = 0.f;

    const int arow = wm * 32 + (lane & 15);
    const int ak8  = (lane >> 4) * 8;
    const int brow = wn * 32 + (lane >> 4) * 8 + (lane & 7);
    const int bk8  = ((lane >> 3) & 1) * 8;

    const int NC = K_ / 64;
    for (int c = 0; c < NC; c++) {
        if (c + 1 < NC) {
            const unsigned bb = sb + ((c + 1) & 1) * GEMM_BUF;
            const int ko = (c + 1) * 64;
            #pragma unroll
            for (int i = 0; i < 4; i++) {
                unsigned d = bb + as_[i];
                size_t g = (size_t)(m0 + ar[i]) * K_ + ko + asg[i];
                cpa16(d,         Ah + g);
                cpa16(d + 18432, Al + g);
            }
            #pragma unroll
            for (int i = 0; i < 2; i++) {
                unsigned d = bb + 36864 + bs_[i];
                size_t g = (size_t)(n0 + br[i]) * K_ + ko + bsg[i];
                cpa16(d,        Wh + g);
                cpa16(d + 9216, Wl + g);
            }
            cpa_commit();
            cpa_wait<1>();
        } else {
            cpa_wait<0>();
        }
        __syncthreads();

        const unsigned ab = sb + (c & 1) * GEMM_BUF;
        #pragma unroll
        for (int ks = 0; ks < 4; ks++) {
            unsigned ah[2][4], al[2][4], bh4[2][4], bl4[2][4];
            #pragma unroll
            for (int mi = 0; mi < 2; mi++) {
                unsigned off = ab + ((arow + mi * 16) * 72 + ks * 16 + ak8) * 2;
                ldsm4(ah[mi][0], ah[mi][1], ah[mi][2], ah[mi][3], off);
                ldsm4(al[mi][0], al[mi][1], al[mi][2], al[mi][3], off + 18432);
            }
            #pragma unroll
            for (int p = 0; p < 2; p++) {
                unsigned off = ab + 36864 + ((brow + p * 16) * 72 + ks * 16 + bk8) * 2;
                ldsm4(bh4[p][0], bh4[p][1], bh4[p][2], bh4[p][3], off);
                ldsm4(bl4[p][0], bl4[p][1], bl4[p][2], bl4[p][3], off + 9216);
            }
            // pass 1: hh (8 independent)
            #pragma unroll
            for (int mi = 0; mi < 2; mi++)
                #pragma unroll
                for (int nt = 0; nt < 4; nt++) {
                    int p = nt >> 1, u = (nt & 1) * 2;
                    mma16816(acc[mi][nt], ah[mi][0], ah[mi][1], ah[mi][2], ah[mi][3],
                             bh4[p][u], bh4[p][u + 1]);
                }
            // pass 2: hl
            #pragma unroll
            for (int mi = 0; mi < 2; mi++)
                #pragma unroll
                for (int nt = 0; nt < 4; nt++) {
                    int p = nt >> 1, u = (nt & 1) * 2;
                    mma16816(acc[mi][nt], ah[mi][0], ah[mi][1], ah[mi][2], ah[mi][3],
                             bl4[p][u], bl4[p][u + 1]);
                }
            // pass 3: lh
            #pragma unroll
            for (int mi = 0; mi < 2; mi++)
                #pragma unroll
                for (int nt = 0; nt < 4; nt++) {
                    int p = nt >> 1, u = (nt & 1) * 2;
                    mma16816(acc[mi][nt], al[mi][0], al[mi][1], al[mi][2], al[mi][3],
                             bh4[p][u], bh4[p][u + 1]);
                }
        }
        __syncthreads();
    }

    #pragma unroll
    for (int mi = 0; mi < 2; mi++) {
        const int row = m0 + wm * 32 + mi * 16 + (lane >> 2);
        #pragma unroll
        for (int nt = 0; nt < 4; nt++) {
            const int cg = n0 + wn * 32 + nt * 8 + (lane & 3) * 2;
            float2 bv = *(const float2*)(bias + cg);
            if (QKV) {
                const float scl = (sel == 0) ? 0.125f : 1.0f;
                const int nl = cg - (sel << 10);
                const int h = nl >> 6, d = nl & 63;
                const int bb2 = row >> 11, s = row & (S_ - 1);
                size_t base = ((size_t)((sel * 32 + bb2 * H_ + h) * S_ + s)) * D_ + d;
                unsigned hw, lw;
                splitpk((acc[mi][nt][0] + bv.x) * scl, (acc[mi][nt][1] + bv.y) * scl, hw, lw);
                *(unsigned*)(g_sh + base) = hw;
                *(unsigned*)(g_sl + base) = lw;
                splitpk((acc[mi][nt][2] + bv.x) * scl, (acc[mi][nt][3] + bv.y) * scl, hw, lw);
                *(unsigned*)(g_sh + base + 8 * D_) = hw;
                *(unsigned*)(g_sl + base + 8 * D_) = lw;
            } else {
                *(float2*)(out + (size_t)row * E_ + cg) =
                    make_float2(acc[mi][nt][0] + bv.x, acc[mi][nt][1] + bv.y);
                *(float2*)(out + (size_t)(row + 8) * E_ + cg) =
                    make_float2(acc[mi][nt][2] + bv.x, acc[mi][nt][3] + bv.y);
            }
        }
    }
}

// ---------------------------------------------------------------------------
// Flash attention, bf16x3 mma.sync. BR=64, BC=64, 128 threads, 3 CTAs/SM.
// R11: QK and PV MMA loops restructured into 3 independent passes.
// ---------------------------------------------------------------------------
#define FL_BUF  36864
#define FL_SMEM (2 * FL_BUF)

__global__ void __launch_bounds__(128, 3) flash_mma(const float* __restrict__ mask)
{
    extern __shared__ __align__(1024) __nv_bfloat16 smf[];
    const unsigned sb = cvta_s(smf);

    const int tid = threadIdx.x, lane = tid & 31, wid = tid >> 5;
    const int bh = blockIdx.y;                 // b*H + h
    const int row0 = blockIdx.x * 64;
    const int b = bh >> 4, h = bh & 15;

    const __nv_bfloat16* qhb = g_sh + ((size_t)bh * S_ + row0) * D_;
    const __nv_bfloat16* qlb = g_sl + ((size_t)bh * S_ + row0) * D_;
    const __nv_bfloat16* khb = g_sh + (size_t)(32 + bh) * S_ * D_;
    const __nv_bfloat16* klb = g_sl + (size_t)(32 + bh) * S_ * D_;
    const __nv_bfloat16* vhb = g_sh + (size_t)(64 + bh) * S_ * D_;
    const __nv_bfloat16* vlb = g_sl + (size_t)(64 + bh) * S_ * D_;

    int kr[4], kso[4], kgf[4];
    #pragma unroll
    for (int i = 0; i < 4; i++) {
        int idx = tid + 128 * i;
        kr[i] = idx >> 3;
        kso[i] = (idx >> 3) * 144 + (idx & 7) * 16;
        kgf[i] = (idx & 7) * 8;
    }

    // group 0: KV t=0 -> buf0
    #pragma unroll
    for (int i = 0; i < 4; i++) {
        unsigned d = sb + kso[i];
        size_t g = (size_t)kr[i] * D_ + kgf[i];
        cpa16(d,         khb + g);
        cpa16(d + 9216,  klb + g);
        cpa16(d + 18432, vhb + g);
        cpa16(d + 27648, vlb + g);
    }
    cpa_commit();
    // group 1: Q -> buf1 region
    #pragma unroll
    for (int i = 0; i < 4; i++) {
        unsigned d = sb + FL_BUF + kso[i];
        size_t g = (size_t)kr[i] * D_ + kgf[i];
        cpa16(d,        qhb + g);
        cpa16(d + 9216, qlb + g);
    }
    cpa_commit();
    cpa_wait<0>();
    __syncthreads();

    unsigned qh[4][4], ql[4][4];
    {
        const int qrow = wid * 16 + (lane & 15);
        const int qk8 = (lane >> 4) * 8;
        #pragma unroll
        for (int ks = 0; ks < 4; ks++) {
            unsigned off = sb + FL_BUF + (qrow * 72 + ks * 16 + qk8) * 2;
            ldsm4(qh[ks][0], qh[ks][1], qh[ks][2], qh[ks][3], off);
            ldsm4(ql[ks][0], ql[ks][1], ql[ks][2], ql[ks][3], off + 9216);
        }
    }
    __syncthreads();   // all Q reads done before t=1 prefetch overwrites buf1

    float O[8][4];
    #pragma unroll
    for (int nt = 0; nt < 8; nt++)
        #pragma unroll
        for (int q = 0; q < 4; q++) O[nt][q] = 0.f;
    float mr0 = -1e30f, mr1 = -1e30f, lr0 = 0.f, lr1 = 0.f;

    const int krow = (lane >> 4) * 8 + (lane & 7);       // + p*16
    const int kk8  = ((lane >> 3) & 1) * 8;
    const int vrow = ((lane >> 3) & 1) * 8 + (lane & 7); // + ks*16
    const int vc8  = (lane >> 4) * 8;                    // + p*16

    const int r1 = row0 + wid * 16 + (lane >> 2);
    const float* mrow1 = mask + (size_t)r1 * S_;
    const float* mrow2 = mrow1 + 8 * S_;

    const int NT = S_ / 64;   // 32
    for (int t = 0; t < NT; t++) {
        // hoisted mask loads
        const int cb = t * 64 + (lane & 3) * 2;
        float2 mk1[8], mk2[8];
        #pragma unroll
        for (int nt = 0; nt < 8; nt++) {
            mk1[nt] = *(const float2*)(mrow1 + cb + nt * 8);
            mk2[nt] = *(const float2*)(mrow2 + cb + nt * 8);
        }

        if (t + 1 < NT) {
            const unsigned bb = sb + ((t + 1) & 1) * FL_BUF;
            #pragma unroll
            for (int i = 0; i < 4; i++) {
                unsigned d = bb + kso[i];
                size_t g = (size_t)((t + 1) * 64 + kr[i]) * D_ + kgf[i];
                cpa16(d,         khb + g);
                cpa16(d + 9216,  klb + g);
                cpa16(d + 18432, vhb + g);
                cpa16(d + 27648, vlb + g);
            }
            cpa_commit();
            cpa_wait<1>();
        } else {
            cpa_wait<0>();
        }
        __syncthreads();

        const unsigned kbb = sb + (t & 1) * FL_BUF;
        const unsigned vbb = kbb + 18432;

        // ---- S = Q K^T : 3 passes ----
        float sa[8][4];
        #pragma unroll
        for (int nt = 0; nt < 8; nt++)
            #pragma unroll
            for (int q = 0; q < 4; q++) sa[nt][q] = 0.f;

        #pragma unroll
        for (int ks = 0; ks < 4; ks++) {
            unsigned bh4[4][4], bl4[4][4];
            #pragma unroll
            for (int p = 0; p < 4; p++) {
                unsigned off = kbb + ((krow + p * 16) * 72 + ks * 16 + kk8) * 2;
                ldsm4(bh4[p][0], bh4[p][1], bh4[p][2], bh4[p][3], off);
                ldsm4(bl4[p][0], bl4[p][1], bl4[p][2], bl4[p][3], off + 9216);
            }
            #pragma unroll
            for (int nt = 0; nt < 8; nt++) {
                int p = nt >> 1, u = (nt & 1) * 2;
                mma16816(sa[nt], qh[ks][0], qh[ks][1], qh[ks][2], qh[ks][3],
                         bh4[p][u], bh4[p][u + 1]);
            }
            #pragma unroll
            for (int nt = 0; nt < 8; nt++) {
                int p = nt >> 1, u = (nt & 1) * 2;
                mma16816(sa[nt], qh[ks][0], qh[ks][1], qh[ks][2], qh[ks][3],
                         bl4[p][u], bl4[p][u + 1]);
            }
            #pragma unroll
            for (int nt = 0; nt < 8; nt++) {
                int p = nt >> 1, u = (nt & 1) * 2;
                mma16816(sa[nt], ql[ks][0], ql[ks][1], ql[ks][2], ql[ks][3],
                         bh4[p][u], bh4[p][u + 1]);
            }
        }

        // ---- mask + online softmax (warp-local) ----
        float mx0 = -1e30f, mx1 = -1e30f;
        #pragma unroll
        for (int nt = 0; nt < 8; nt++) {
            sa[nt][0] += mk1[nt].x; sa[nt][1] += mk1[nt].y;
            sa[nt][2] += mk2[nt].x; sa[nt][3] += mk2[nt].y;
            mx0 = fmaxf(mx0, fmaxf(sa[nt][0], sa[nt][1]));
            mx1 = fmaxf(mx1, fmaxf(sa[nt][2], sa[nt][3]));
        }
        mx0 = fmaxf(mx0, __shfl_xor_sync(0xffffffffu, mx0, 1));
        mx0 = fmaxf(mx0, __shfl_xor_sync(0xffffffffu, mx0, 2));
        mx1 = fmaxf(mx1, __shfl_xor_sync(0xffffffffu, mx1, 1));
        mx1 = fmaxf(mx1, __shfl_xor_sync(0xffffffffu, mx1, 2));

        float mn0 = fmaxf(mr0, mx0), mn1 = fmaxf(mr1, mx1);
        float a0 = __expf(mr0 - mn0), a1 = __expf(mr1 - mn1);
        mr0 = mn0; mr1 = mn1;

        float s0 = 0.f, s1 = 0.f;
        #pragma unroll
        for (int nt = 0; nt < 8; nt++) {
            sa[nt][0] = __expf(sa[nt][0] - mn0); s0 += sa[nt][0];
            sa[nt][1] = __expf(sa[nt][1] - mn0); s0 += sa[nt][1];
            sa[nt][2] = __expf(sa[nt][2] - mn1); s1 += sa[nt][2];
            sa[nt][3] = __expf(sa[nt][3] - mn1); s1 += sa[nt][3];
        }
        s0 += __shfl_xor_sync(0xffffffffu, s0, 1);
        s0 += __shfl_xor_sync(0xffffffffu, s0, 2);
        s1 += __shfl_xor_sync(0xffffffffu, s1, 1);
        s1 += __shfl_xor_sync(0xffffffffu, s1, 2);
        lr0 = lr0 * a0 + s0;
        lr1 = lr1 * a1 + s1;
        #pragma unroll
        for (int nt = 0; nt < 8; nt++) {
            O[nt][0] *= a0; O[nt][1] *= a0;
            O[nt][2] *= a1; O[nt][3] *= a1;
        }

        // ---- O += P V : build P frags, then 3 passes ----
        #pragma unroll
        for (int ks = 0; ks < 4; ks++) {
            int j0 = 2 * ks, j1 = j0 + 1;
            unsigned ph0, ph1, ph2, ph3, pl0, pl1, pl2, pl3;
            splitpk(sa[j0][0], sa[j0][1], ph0, pl0);
            splitpk(sa[j0][2], sa[j0][3], ph1, pl1);
            splitpk(sa[j1][0], sa[j1][1], ph2, pl2);
            splitpk(sa[j1][2], sa[j1][3], ph3, pl3);
            unsigned vh4[4][4], vl4[4][4];
            #pragma unroll
            for (int p = 0; p < 4; p++) {
                unsigned off = vbb + ((vrow + ks * 16) * 72 + vc8 + p * 16) * 2;
                ldsm4t(vh4[p][0], vh4[p][1], vh4[p][2], vh4[p][3], off);
                ldsm4t(vl4[p][0], vl4[p][1], vl4[p][2], vl4[p][3], off + 9216);
            }
            #pragma unroll
            for (int nt = 0; nt < 8; nt++) {
                int p = nt >> 1, u = (nt & 1) * 2;
                mma16816(O[nt], ph0, ph1, ph2, ph3, vh4[p][u], vh4[p][u + 1]);
            }
            #pragma unroll
            for (int nt = 0; nt < 8; nt++) {
                int p = nt >> 1, u = (nt & 1) * 2;
                mma16816(O[nt], ph0, ph1, ph2, ph3, vl4[p][u], vl4[p][u + 1]);
            }
            #pragma unroll
            for (int nt = 0; nt < 8; nt++) {
                int p = nt >> 1, u = (nt & 1) * 2;
                mma16816(O[nt], pl0, pl1, pl2, pl3, vh4[p][u], vh4[p][u + 1]);
            }
        }
        __syncthreads();
    }

    // ---- Epilogue: normalize, split, write ctx hi/lo ----
    float i0 = 1.f / lr0, i1 = 1.f / lr1;
    size_t o1 = ((size_t)(b * S_ + r1)) * E_ + h * D_ + (lane & 3) * 2;
    size_t o2 = o1 + (size_t)8 * E_;
    #pragma unroll
    for (int nt = 0; nt < 8; nt++) {
        unsigned hw, lw;
        splitpk(O[nt][0] * i0, O[nt][1] * i0, hw, lw);
        *(unsigned*)(g_ch + o1 + nt * 8) = hw;
        *(unsigned*)(g_cl + o1 + nt * 8) = lw;
        splitpk(O[nt][2] * i1, O[nt][3] * i1, hw, lw);
        *(unsigned*)(g_ch + o2 + nt * 8) = hw;
        *(unsigned*)(g_cl + o2 + nt * 8) = lw;
    }
}

// ---------------------------------------------------------------------------
// Launch: split pass -> QKV GEMM -> flash -> output GEMM.
// ---------------------------------------------------------------------------
extern "C" void kernel_launch(void* const* d_in, const int* in_sizes, int n_in,
                              void* d_out, int out_size)
{
    const float* query = (const float*)d_in[0];
    const float* key   = (const float*)d_in[1];
    const float* value = (const float*)d_in[2];
    const float* qkvw  = (const float*)d_in[3];
    const float* qkvb  = (const float*)d_in[4];
    const float* projw = (const float*)d_in[5];
    const float* projb = (const float*)d_in[6];
    const float* mask  = (const float*)d_in[7];

    __nv_bfloat16 *xh, *xl, *wh, *wl, *ch, *cl;
    cudaGetSymbolAddress((void**)&xh, g_xh);
    cudaGetSymbolAddress((void**)&xl, g_xl);
    cudaGetSymbolAddress((void**)&wh, g_wh);
    cudaGetSymbolAddress((void**)&wl, g_wl);
    cudaGetSymbolAddress((void**)&ch, g_ch);
    cudaGetSymbolAddress((void**)&cl, g_cl);

    cudaFuncSetAttribute(gemm_bf16<1>, cudaFuncAttributeMaxDynamicSharedMemorySize, GEMM_SMEM);
    cudaFuncSetAttribute(gemm_bf16<0>, cudaFuncAttributeMaxDynamicSharedMemorySize, GEMM_SMEM);
    cudaFuncSetAttribute(flash_mma, cudaFuncAttributeMaxDynamicSharedMemorySize, FL_SMEM);

    // 1. split inputs + weights to bf16 hi/lo
    split_all<<<16384, 256>>>(query, key, value, qkvw, projw);

    // 2. fused QKV projection -> per-head split q/k/v   (48 x 32 = 1536 CTAs)
    gemm_bf16<1><<<dim3(48, 32), 256, GEMM_SMEM>>>(xh, xl, wh, wl, qkvb, nullptr);

    // 3. flash attention -> split ctx                   (32 x 32 = 1024 CTAs)
    flash_mma<<<dim3(S_ / 64, B_ * H_), 128, FL_SMEM>>>(mask);

    // 4. output projection -> fp32 d_out                (16 x 32 = 512 CTAs)
    gemm_bf16<0><<<dim3(16, 32), 256, GEMM_SMEM>>>(ch, cl,
                                                   wh + (size_t)3 * K_ * K_,
                                                   wl + (size_t)3 * K_ * K_,
                                                   projb, (float*)d_out);
}

// round 13
// speedup vs baseline: 1.3649x; 1.3649x over previous
#include <cuda_runtime.h>
#include <cuda_fp16.h>

#define B_ 2
#define S_ 2048
#define E_ 1024
#define H_ 16
#define D_ 64
#define M_ 4096
#define K_ 1024

// ---------------------------------------------------------------------------
// Scratch (__device__ globals). fp16: A-side split hi/lo, B-side rounded hi.
// ---------------------------------------------------------------------------
__device__ __align__(256) __half g_xh[(size_t)3*M_*K_];   // split q/k/v inputs (hi)
__device__ __align__(256) __half g_xl[(size_t)3*M_*K_];   // (lo)
__device__ __align__(256) __half g_wh[(size_t)4*K_*K_];   // qkvw + projw, rounded
__device__ __align__(256) __half g_sh[(size_t)3*B_*H_*S_*D_]; // q/k/v heads (hi)
__device__ __align__(256) __half g_sl[(size_t)3*B_*H_*S_*D_]; // q lo (k/v lo unused)
__device__ __align__(256) __half g_ch[(size_t)M_*E_];     // ctx hi
__device__ __align__(256) __half g_cl[(size_t)M_*E_];     // ctx lo

// ---------------------------------------------------------------------------
// Helpers
// ---------------------------------------------------------------------------
__device__ __forceinline__ unsigned cvta_s(const void* p) {
    return (unsigned)__cvta_generic_to_shared(p);
}
__device__ __forceinline__ unsigned pkh2(__half a, __half b) {
    return (unsigned)__half_as_ushort(a) | ((unsigned)__half_as_ushort(b) << 16);
}
// fp16 split: x = h + l (h = rn(x), l = rn(x - h)); pack pairs.
__device__ __forceinline__ void splitpk(float x, float y, unsigned& h, unsigned& l) {
    __half hx = __float2half_rn(x);
    __half hy = __float2half_rn(y);
    float rx = x - __half2float(hx);
    float ry = y - __half2float(hy);
    h = pkh2(hx, hy);
    l = pkh2(__float2half_rn(rx), __float2half_rn(ry));
}
__device__ __forceinline__ unsigned rnd2(float x, float y) {
    return pkh2(__float2half_rn(x), __float2half_rn(y));
}
__device__ __forceinline__ void ldsm4(unsigned& r0, unsigned& r1, unsigned& r2, unsigned& r3,
                                      unsigned a) {
    asm volatile("ldmatrix.sync.aligned.m8n8.x4.shared.b16 {%0,%1,%2,%3}, [%4];"
                 : "=r"(r0), "=r"(r1), "=r"(r2), "=r"(r3) : "r"(a));
}
__device__ __forceinline__ void ldsm4t(unsigned& r0, unsigned& r1, unsigned& r2, unsigned& r3,
                                       unsigned a) {
    asm volatile("ldmatrix.sync.aligned.m8n8.x4.trans.shared.b16 {%0,%1,%2,%3}, [%4];"
                 : "=r"(r0), "=r"(r1), "=r"(r2), "=r"(r3) : "r"(a));
}
// fp16 operands, fp32 accumulator. Non-volatile (pure register op).
__device__ __forceinline__ void mma16816(float* c,
                                         unsigned a0, unsigned a1, unsigned a2, unsigned a3,
                                         unsigned b0, unsigned b1) {
    asm("mma.sync.aligned.m16n8k16.row.col.f32.f16.f16.f32 "
        "{%0,%1,%2,%3}, {%4,%5,%6,%7}, {%8,%9}, {%0,%1,%2,%3};"
        : "+f"(c[0]), "+f"(c[1]), "+f"(c[2]), "+f"(c[3])
        : "r"(a0), "r"(a1), "r"(a2), "r"(a3), "r"(b0), "r"(b1));
}
__device__ __forceinline__ void cpa16(unsigned dst, const void* src) {
    asm volatile("cp.async.cg.shared.global [%0], [%1], 16;" :: "r"(dst), "l"(src));
}
__device__ __forceinline__ void cpa_commit() {
    asm volatile("cp.async.commit_group;" ::: "memory");
}
template<int N>
__device__ __forceinline__ void cpa_wait() {
    asm volatile("cp.async.wait_group %0;" :: "n"(N) : "memory");
}

// ---------------------------------------------------------------------------
// Split pass: x inputs -> fp16 hi/lo; weights -> fp16 rounded (hi only).
// ---------------------------------------------------------------------------
__global__ void __launch_bounds__(256) split_all(
    const float* __restrict__ q, const float* __restrict__ k, const float* __restrict__ v,
    const float* __restrict__ qkvw, const float* __restrict__ projw)
{
    size_t i4 = (size_t)blockIdx.x * 256 + threadIdx.x;
    const size_t XQ = (size_t)M_ * K_ / 4;          // 1M float4 per x input
    const size_t WQ = (size_t)3 * K_ * K_ / 4;      // qkvw float4 count
    if (i4 < 3 * XQ) {
        size_t sel = i4 / XQ, o = i4 - sel * XQ;
        const float* src = (sel == 0) ? q : ((sel == 1) ? k : v);
        __half* dh = g_xh + sel * (size_t)M_ * K_;
        __half* dl = g_xl + sel * (size_t)M_ * K_;
        float4 x = *((const float4*)src + o);
        unsigned h0, l0, h1, l1;
        splitpk(x.x, x.y, h0, l0);
        splitpk(x.z, x.w, h1, l1);
        *(uint2*)(dh + o * 4) = make_uint2(h0, h1);
        *(uint2*)(dl + o * 4) = make_uint2(l0, l1);
    } else {
        size_t j = i4 - 3 * XQ;
        const float* src; size_t o; __half* dh;
        if (j < WQ) { src = qkvw; o = j; dh = g_wh; }
        else        { src = projw; o = j - WQ; dh = g_wh + (size_t)3 * K_ * K_; }
        float4 x = *((const float4*)src + o);
        *(uint2*)(dh + o * 4) = make_uint2(rnd2(x.x, x.y), rnd2(x.z, x.w));
    }
}

// ---------------------------------------------------------------------------
// fp16x2 GEMM: C[m][n] = sum_k A[m][k]*W[n][k] (+bias); A split hi/lo, W
// rounded. 2 MMAs per logical MMA (Ah*Wh + Al*Wh).
// CTA 128m x 64n, 8 warps, warp tile 32x32. K-chunk 64, cp.async double
// buffered. Buffer 46080 B; 2 buffers = 92160 -> 2 CTAs/SM.
// ---------------------------------------------------------------------------
#define GEMM_BUF  46080
#define GEMM_SMEM (2 * GEMM_BUF)

template<int QKV>
__global__ void __launch_bounds__(256, 2) gemm_f16(
    const __half* __restrict__ Ah0, const __half* __restrict__ Al0,
    const __half* __restrict__ Wh,
    const float* __restrict__ bias, float* __restrict__ out)
{
    extern __shared__ __align__(1024) __half smg[];
    const unsigned sb = cvta_s(smg);

    const int tid = threadIdx.x, lane = tid & 31, wid = tid >> 5;
    const int wm = wid & 3, wn = wid >> 2;
    const int m0 = blockIdx.y * 128, n0 = blockIdx.x * 64;

    const __half* Ah = Ah0;
    const __half* Al = Al0;
    int sel = 0;
    if (QKV) {
        sel = n0 >> 10;
        Ah += (size_t)sel * M_ * K_;
        Al += (size_t)sel * M_ * K_;
    }

    int ar[4], as_[4], asg[4];
    #pragma unroll
    for (int i = 0; i < 4; i++) {
        int idx = tid + 256 * i;
        ar[i] = idx >> 3;
        asg[i] = (idx & 7) * 8;
        as_[i] = (idx >> 3) * 144 + (idx & 7) * 16;
    }
    int br[2], bs_[2], bsg[2];
    #pragma unroll
    for (int i = 0; i < 2; i++) {
        int idx = tid + 256 * i;
        br[i] = idx >> 3;
        bsg[i] = (idx & 7) * 8;
        bs_[i] = (idx >> 3) * 144 + (idx & 7) * 16;
    }

    #pragma unroll
    for (int i = 0; i < 4; i++) {
        unsigned d = sb + as_[i];
        size_t g = (size_t)(m0 + ar[i]) * K_ + asg[i];
        cpa16(d,         Ah + g);
        cpa16(d + 18432, Al + g);
    }
    #pragma unroll
    for (int i = 0; i < 2; i++) {
        unsigned d = sb + 36864 + bs_[i];
        cpa16(d, Wh + (size_t)(n0 + br[i]) * K_ + bsg[i]);
    }
    cpa_commit();

    float acc[2][4][4];
    #pragma unroll
    for (int mi = 0; mi < 2; mi++)
        #pragma unroll
        for (int nt = 0; nt < 4; nt++)
            #pragma unroll
            for (int q = 0; q < 4; q++) acc[mi][nt][q] = 0.f;

    const int arow = wm * 32 + (lane & 15);
    const int ak8  = (lane >> 4) * 8;
    const int brow = wn * 32 + (lane >> 4) * 8 + (lane & 7);
    const int bk8  = ((lane >> 3) & 1) * 8;

    const int NC = K_ / 64;
    for (int c = 0; c < NC; c++) {
        if (c + 1 < NC) {
            const unsigned bb = sb + ((c + 1) & 1) * GEMM_BUF;
            const int ko = (c + 1) * 64;
            #pragma unroll
            for (int i = 0; i < 4; i++) {
                unsigned d = bb + as_[i];
                size_t g = (size_t)(m0 + ar[i]) * K_ + ko + asg[i];
                cpa16(d,         Ah + g);
                cpa16(d + 18432, Al + g);
            }
            #pragma unroll
            for (int i = 0; i < 2; i++) {
                unsigned d = bb + 36864 + bs_[i];
                cpa16(d, Wh + (size_t)(n0 + br[i]) * K_ + ko + bsg[i]);
            }
            cpa_commit();
            cpa_wait<1>();
        } else {
            cpa_wait<0>();
        }
        __syncthreads();

        const unsigned ab = sb + (c & 1) * GEMM_BUF;
        #pragma unroll
        for (int ks = 0; ks < 4; ks++) {
            unsigned ah[2][4], al[2][4], bh4[2][4];
            #pragma unroll
            for (int mi = 0; mi < 2; mi++) {
                unsigned off = ab + ((arow + mi * 16) * 72 + ks * 16 + ak8) * 2;
                ldsm4(ah[mi][0], ah[mi][1], ah[mi][2], ah[mi][3], off);
                ldsm4(al[mi][0], al[mi][1], al[mi][2], al[mi][3], off + 18432);
            }
            #pragma unroll
            for (int p = 0; p < 2; p++) {
                unsigned off = ab + 36864 + ((brow + p * 16) * 72 + ks * 16 + bk8) * 2;
                ldsm4(bh4[p][0], bh4[p][1], bh4[p][2], bh4[p][3], off);
            }
            // pass 1: hi*W (8 independent)
            #pragma unroll
            for (int mi = 0; mi < 2; mi++)
                #pragma unroll
                for (int nt = 0; nt < 4; nt++) {
                    int p = nt >> 1, u = (nt & 1) * 2;
                    mma16816(acc[mi][nt], ah[mi][0], ah[mi][1], ah[mi][2], ah[mi][3],
                             bh4[p][u], bh4[p][u + 1]);
                }
            // pass 2: lo*W
            #pragma unroll
            for (int mi = 0; mi < 2; mi++)
                #pragma unroll
                for (int nt = 0; nt < 4; nt++) {
                    int p = nt >> 1, u = (nt & 1) * 2;
                    mma16816(acc[mi][nt], al[mi][0], al[mi][1], al[mi][2], al[mi][3],
                             bh4[p][u], bh4[p][u + 1]);
                }
        }
        __syncthreads();
    }

    // Epilogue
    #pragma unroll
    for (int mi = 0; mi < 2; mi++) {
        const int row = m0 + wm * 32 + mi * 16 + (lane >> 2);
        #pragma unroll
        for (int nt = 0; nt < 4; nt++) {
            const int cg = n0 + wn * 32 + nt * 8 + (lane & 3) * 2;
            float2 bv = *(const float2*)(bias + cg);
            if (QKV) {
                const float scl = (sel == 0) ? 0.125f : 1.0f;
                const int nl = cg - (sel << 10);
                const int h = nl >> 6, d = nl & 63;
                const int bb2 = row >> 11, s = row & (S_ - 1);
                size_t base = ((size_t)((sel * 32 + bb2 * H_ + h) * S_ + s)) * D_ + d;
                unsigned hw, lw;
                splitpk((acc[mi][nt][0] + bv.x) * scl, (acc[mi][nt][1] + bv.y) * scl, hw, lw);
                *(unsigned*)(g_sh + base) = hw;
                if (sel == 0) *(unsigned*)(g_sl + base) = lw;
                splitpk((acc[mi][nt][2] + bv.x) * scl, (acc[mi][nt][3] + bv.y) * scl, hw, lw);
                *(unsigned*)(g_sh + base + 8 * D_) = hw;
                if (sel == 0) *(unsigned*)(g_sl + base + 8 * D_) = lw;
            } else {
                *(float2*)(out + (size_t)row * E_ + cg) =
                    make_float2(acc[mi][nt][0] + bv.x, acc[mi][nt][1] + bv.y);
                *(float2*)(out + (size_t)(row + 8) * E_ + cg) =
                    make_float2(acc[mi][nt][2] + bv.x, acc[mi][nt][3] + bv.y);
            }
        }
    }
}

// ---------------------------------------------------------------------------
// Flash attention, fp16x2 mma.sync. BR=64, BC=64, 128 threads, 4 CTAs/SM.
// Q split hi/lo in regs; K,V rounded fp16 (hi only).
// S = Qh*Kh + Ql*Kh;  O += Ph*Vh + Pl*Vh.
// ---------------------------------------------------------------------------
#define FL_BUF  18432
#define FL_SMEM (2 * FL_BUF)

__global__ void __launch_bounds__(128, 4) flash_mma(const float* __restrict__ mask)
{
    extern __shared__ __align__(1024) __half smf[];
    const unsigned sb = cvta_s(smf);

    const int tid = threadIdx.x, lane = tid & 31, wid = tid >> 5;
    const int bh = blockIdx.y;                 // b*H + h
    const int row0 = blockIdx.x * 64;
    const int b = bh >> 4, h = bh & 15;

    const __half* qhb = g_sh + ((size_t)bh * S_ + row0) * D_;
    const __half* qlb = g_sl + ((size_t)bh * S_ + row0) * D_;
    const __half* khb = g_sh + (size_t)(32 + bh) * S_ * D_;
    const __half* vhb = g_sh + (size_t)(64 + bh) * S_ * D_;

    int kr[4], kso[4], kgf[4];
    #pragma unroll
    for (int i = 0; i < 4; i++) {
        int idx = tid + 128 * i;
        kr[i] = idx >> 3;
        kso[i] = (idx >> 3) * 144 + (idx & 7) * 16;
        kgf[i] = (idx & 7) * 8;
    }

    // group 0: KV t=0 -> buf0 (KH +0, VH +9216)
    #pragma unroll
    for (int i = 0; i < 4; i++) {
        unsigned d = sb + kso[i];
        size_t g = (size_t)kr[i] * D_ + kgf[i];
        cpa16(d,        khb + g);
        cpa16(d + 9216, vhb + g);
    }
    cpa_commit();
    // group 1: Q hi/lo -> buf1 region
    #pragma unroll
    for (int i = 0; i < 4; i++) {
        unsigned d = sb + FL_BUF + kso[i];
        size_t g = (size_t)kr[i] * D_ + kgf[i];
        cpa16(d,        qhb + g);
        cpa16(d + 9216, qlb + g);
    }
    cpa_commit();
    cpa_wait<0>();
    __syncthreads();

    unsigned qh[4][4], ql[4][4];
    {
        const int qrow = wid * 16 + (lane & 15);
        const int qk8 = (lane >> 4) * 8;
        #pragma unroll
        for (int ks = 0; ks < 4; ks++) {
            unsigned off = sb + FL_BUF + (qrow * 72 + ks * 16 + qk8) * 2;
            ldsm4(qh[ks][0], qh[ks][1], qh[ks][2], qh[ks][3], off);
            ldsm4(ql[ks][0], ql[ks][1], ql[ks][2], ql[ks][3], off + 9216);
        }
    }
    __syncthreads();   // Q reads done before t=1 prefetch overwrites buf1

    float O[8][4];
    #pragma unroll
    for (int nt = 0; nt < 8; nt++)
        #pragma unroll
        for (int q = 0; q < 4; q++) O[nt][q] = 0.f;
    float mr0 = -1e30f, mr1 = -1e30f, lr0 = 0.f, lr1 = 0.f;

    const int krow = (lane >> 4) * 8 + (lane & 7);       // + p*16
    const int kk8  = ((lane >> 3) & 1) * 8;
    const int vrow = ((lane >> 3) & 1) * 8 + (lane & 7); // + ks*16
    const int vc8  = (lane >> 4) * 8;                    // + p*16

    const int r1 = row0 + wid * 16 + (lane >> 2);
    const float* mrow1 = mask + (size_t)r1 * S_;
    const float* mrow2 = mrow1 + 8 * S_;

    const int NT = S_ / 64;   // 32
    for (int t = 0; t < NT; t++) {
        // hoisted mask loads
        const int cb = t * 64 + (lane & 3) * 2;
        float2 mk1[8], mk2[8];
        #pragma unroll
        for (int nt = 0; nt < 8; nt++) {
            mk1[nt] = *(const float2*)(mrow1 + cb + nt * 8);
            mk2[nt] = *(const float2*)(mrow2 + cb + nt * 8);
        }

        if (t + 1 < NT) {
            const unsigned bb = sb + ((t + 1) & 1) * FL_BUF;
            #pragma unroll
            for (int i = 0; i < 4; i++) {
                unsigned d = bb + kso[i];
                size_t g = (size_t)((t + 1) * 64 + kr[i]) * D_ + kgf[i];
                cpa16(d,        khb + g);
                cpa16(d + 9216, vhb + g);
            }
            cpa_commit();
            cpa_wait<1>();
        } else {
            cpa_wait<0>();
        }
        __syncthreads();

        const unsigned kbb = sb + (t & 1) * FL_BUF;
        const unsigned vbb = kbb + 9216;

        // ---- S = Qh K + Ql K ----
        float sa[8][4];
        #pragma unroll
        for (int nt = 0; nt < 8; nt++)
            #pragma unroll
            for (int q = 0; q < 4; q++) sa[nt][q] = 0.f;

        #pragma unroll
        for (int ks = 0; ks < 4; ks++) {
            unsigned bh4[4][4];
            #pragma unroll
            for (int p = 0; p < 4; p++) {
                unsigned off = kbb + ((krow + p * 16) * 72 + ks * 16 + kk8) * 2;
                ldsm4(bh4[p][0], bh4[p][1], bh4[p][2], bh4[p][3], off);
            }
            #pragma unroll
            for (int nt = 0; nt < 8; nt++) {
                int p = nt >> 1, u = (nt & 1) * 2;
                mma16816(sa[nt], qh[ks][0], qh[ks][1], qh[ks][2], qh[ks][3],
                         bh4[p][u], bh4[p][u + 1]);
            }
            #pragma unroll
            for (int nt = 0; nt < 8; nt++) {
                int p = nt >> 1, u = (nt & 1) * 2;
                mma16816(sa[nt], ql[ks][0], ql[ks][1], ql[ks][2], ql[ks][3],
                         bh4[p][u], bh4[p][u + 1]);
            }
        }

        // ---- mask + online softmax (warp-local) ----
        float mx0 = -1e30f, mx1 = -1e30f;
        #pragma unroll
        for (int nt = 0; nt < 8; nt++) {
            sa[nt][0] += mk1[nt].x; sa[nt][1] += mk1[nt].y;
            sa[nt][2] += mk2[nt].x; sa[nt][3] += mk2[nt].y;
            mx0 = fmaxf(mx0, fmaxf(sa[nt][0], sa[nt][1]));
            mx1 = fmaxf(mx1, fmaxf(sa[nt][2], sa[nt][3]));
        }
        mx0 = fmaxf(mx0, __shfl_xor_sync(0xffffffffu, mx0, 1));
        mx0 = fmaxf(mx0, __shfl_xor_sync(0xffffffffu, mx0, 2));
        mx1 = fmaxf(mx1, __shfl_xor_sync(0xffffffffu, mx1, 1));
        mx1 = fmaxf(mx1, __shfl_xor_sync(0xffffffffu, mx1, 2));

        float mn0 = fmaxf(mr0, mx0), mn1 = fmaxf(mr1, mx1);
        float a0 = __expf(mr0 - mn0), a1 = __expf(mr1 - mn1);
        mr0 = mn0; mr1 = mn1;

        float s0 = 0.f, s1 = 0.f;
        #pragma unroll
        for (int nt = 0; nt < 8; nt++) {
            sa[nt][0] = __expf(sa[nt][0] - mn0); s0 += sa[nt][0];
            sa[nt][1] = __expf(sa[nt][1] - mn0); s0 += sa[nt][1];
            sa[nt][2] = __expf(sa[nt][2] - mn1); s1 += sa[nt][2];
            sa[nt][3] = __expf(sa[nt][3] - mn1); s1 += sa[nt][3];
        }
        s0 += __shfl_xor_sync(0xffffffffu, s0, 1);
        s0 += __shfl_xor_sync(0xffffffffu, s0, 2);
        s1 += __shfl_xor_sync(0xffffffffu, s1, 1);
        s1 += __shfl_xor_sync(0xffffffffu, s1, 2);
        lr0 = lr0 * a0 + s0;
        lr1 = lr1 * a1 + s1;
        #pragma unroll
        for (int nt = 0; nt < 8; nt++) {
            O[nt][0] *= a0; O[nt][1] *= a0;
            O[nt][2] *= a1; O[nt][3] *= a1;
        }

        // ---- O += Ph V + Pl V ----
        #pragma unroll
        for (int ks = 0; ks < 4; ks++) {
            int j0 = 2 * ks, j1 = j0 + 1;
            unsigned ph0, ph1, ph2, ph3, pl0, pl1, pl2, pl3;
            splitpk(sa[j0][0], sa[j0][1], ph0, pl0);
            splitpk(sa[j0][2], sa[j0][3], ph1, pl1);
            splitpk(sa[j1][0], sa[j1][1], ph2, pl2);
            splitpk(sa[j1][2], sa[j1][3], ph3, pl3);
            unsigned vh4[4][4];
            #pragma unroll
            for (int p = 0; p < 4; p++) {
                unsigned off = vbb + ((vrow + ks * 16) * 72 + vc8 + p * 16) * 2;
                ldsm4t(vh4[p][0], vh4[p][1], vh4[p][2], vh4[p][3], off);
            }
            #pragma unroll
            for (int nt = 0; nt < 8; nt++) {
                int p = nt >> 1, u = (nt & 1) * 2;
                mma16816(O[nt], ph0, ph1, ph2, ph3, vh4[p][u], vh4[p][u + 1]);
            }
            #pragma unroll
            for (int nt = 0; nt < 8; nt++) {
                int p = nt >> 1, u = (nt & 1) * 2;
                mma16816(O[nt], pl0, pl1, pl2, pl3, vh4[p][u], vh4[p][u + 1]);
            }
        }
        __syncthreads();
    }

    // ---- Epilogue: normalize, split, write ctx hi/lo ----
    float i0 = 1.f / lr0, i1 = 1.f / lr1;
    size_t o1 = ((size_t)(b * S_ + r1)) * E_ + h * D_ + (lane & 3) * 2;
    size_t o2 = o1 + (size_t)8 * E_;
    #pragma unroll
    for (int nt = 0; nt < 8; nt++) {
        unsigned hw, lw;
        splitpk(O[nt][0] * i0, O[nt][1] * i0, hw, lw);
        *(unsigned*)(g_ch + o1 + nt * 8) = hw;
        *(unsigned*)(g_cl + o1 + nt * 8) = lw;
        splitpk(O[nt][2] * i1, O[nt][3] * i1, hw, lw);
        *(unsigned*)(g_ch + o2 + nt * 8) = hw;
        *(unsigned*)(g_cl + o2 + nt * 8) = lw;
    }
}

// ---------------------------------------------------------------------------
// Launch: split pass -> QKV GEMM -> flash -> output GEMM.
// ---------------------------------------------------------------------------
extern "C" void kernel_launch(void* const* d_in, const int* in_sizes, int n_in,
                              void* d_out, int out_size)
{
    const float* query = (const float*)d_in[0];
    const float* key   = (const float*)d_in[1];
    const float* value = (const float*)d_in[2];
    const float* qkvw  = (const float*)d_in[3];
    const float* qkvb  = (const float*)d_in[4];
    const float* projw = (const float*)d_in[5];
    const float* projb = (const float*)d_in[6];
    const float* mask  = (const float*)d_in[7];

    __half *xh, *xl, *wh, *ch, *cl;
    cudaGetSymbolAddress((void**)&xh, g_xh);
    cudaGetSymbolAddress((void**)&xl, g_xl);
    cudaGetSymbolAddress((void**)&wh, g_wh);
    cudaGetSymbolAddress((void**)&ch, g_ch);
    cudaGetSymbolAddress((void**)&cl, g_cl);

    cudaFuncSetAttribute(gemm_f16<1>, cudaFuncAttributeMaxDynamicSharedMemorySize, GEMM_SMEM);
    cudaFuncSetAttribute(gemm_f16<0>, cudaFuncAttributeMaxDynamicSharedMemorySize, GEMM_SMEM);
    cudaFuncSetAttribute(flash_mma, cudaFuncAttributeMaxDynamicSharedMemorySize, FL_SMEM);

    // 1. split inputs (hi/lo) + weights (rounded)
    split_all<<<16384, 256>>>(query, key, value, qkvw, projw);

    // 2. fused QKV projection -> per-head q/k/v  (n in [0,3072): 48 blocks)
    gemm_f16<1><<<dim3(48, 32), 256, GEMM_SMEM>>>(xh, xl, wh, qkvb, nullptr);

    // 3. flash attention -> split ctx
    flash_mma<<<dim3(S_ / 64, B_ * H_), 128, FL_SMEM>>>(mask);

    // 4. output projection -> fp32 d_out  (n in [0,1024): 16 blocks — R12 bug was 8)
    gemm_f16<0><<<dim3(16, 32), 256, GEMM_SMEM>>>(ch, cl,
                                                  wh + (size_t)3 * K_ * K_,
                                                  projb, (float*)d_out);
}

// round 14
// speedup vs baseline: 1.4757x; 1.0812x over previous
#include <cuda_runtime.h>
#include <cuda_fp16.h>

#define B_ 2
#define S_ 2048
#define E_ 1024
#define H_ 16
#define D_ 64
#define M_ 4096
#define K_ 1024

// ---------------------------------------------------------------------------
// Scratch (__device__ globals). fp16: GEMM A-side split hi/lo; q/k/v heads,
// weights, K/V rounded to single fp16. ctx split hi/lo (proj accuracy).
// ---------------------------------------------------------------------------
__device__ __align__(256) __half g_xh[(size_t)3*M_*K_];   // split q/k/v inputs (hi)
__device__ __align__(256) __half g_xl[(size_t)3*M_*K_];   // (lo)
__device__ __align__(256) __half g_wh[(size_t)4*K_*K_];   // qkvw + projw, rounded
__device__ __align__(256) __half g_sh[(size_t)3*B_*H_*S_*D_]; // q/k/v heads, rounded
__device__ __align__(256) __half g_ch[(size_t)M_*E_];     // ctx hi
__device__ __align__(256) __half g_cl[(size_t)M_*E_];     // ctx lo

// ---------------------------------------------------------------------------
// Helpers
// ---------------------------------------------------------------------------
__device__ __forceinline__ unsigned cvta_s(const void* p) {
    return (unsigned)__cvta_generic_to_shared(p);
}
__device__ __forceinline__ unsigned pkh2(__half a, __half b) {
    return (unsigned)__half_as_ushort(a) | ((unsigned)__half_as_ushort(b) << 16);
}
// fp16 split: x = h + l (h = rn(x), l = rn(x - h)); pack pairs.
__device__ __forceinline__ void splitpk(float x, float y, unsigned& h, unsigned& l) {
    __half hx = __float2half_rn(x);
    __half hy = __float2half_rn(y);
    float rx = x - __half2float(hx);
    float ry = y - __half2float(hy);
    h = pkh2(hx, hy);
    l = pkh2(__float2half_rn(rx), __float2half_rn(ry));
}
__device__ __forceinline__ unsigned rnd2(float x, float y) {
    return pkh2(__float2half_rn(x), __float2half_rn(y));
}
__device__ __forceinline__ void ldsm4(unsigned& r0, unsigned& r1, unsigned& r2, unsigned& r3,
                                      unsigned a) {
    asm volatile("ldmatrix.sync.aligned.m8n8.x4.shared.b16 {%0,%1,%2,%3}, [%4];"
                 : "=r"(r0), "=r"(r1), "=r"(r2), "=r"(r3) : "r"(a));
}
__device__ __forceinline__ void ldsm4t(unsigned& r0, unsigned& r1, unsigned& r2, unsigned& r3,
                                       unsigned a) {
    asm volatile("ldmatrix.sync.aligned.m8n8.x4.trans.shared.b16 {%0,%1,%2,%3}, [%4];"
                 : "=r"(r0), "=r"(r1), "=r"(r2), "=r"(r3) : "r"(a));
}
// fp16 operands, fp32 accumulator. Non-volatile (pure register op).
__device__ __forceinline__ void mma16816(float* c,
                                         unsigned a0, unsigned a1, unsigned a2, unsigned a3,
                                         unsigned b0, unsigned b1) {
    asm("mma.sync.aligned.m16n8k16.row.col.f32.f16.f16.f32 "
        "{%0,%1,%2,%3}, {%4,%5,%6,%7}, {%8,%9}, {%0,%1,%2,%3};"
        : "+f"(c[0]), "+f"(c[1]), "+f"(c[2]), "+f"(c[3])
        : "r"(a0), "r"(a1), "r"(a2), "r"(a3), "r"(b0), "r"(b1));
}
__device__ __forceinline__ void cpa16(unsigned dst, const void* src) {
    asm volatile("cp.async.cg.shared.global [%0], [%1], 16;" :: "r"(dst), "l"(src));
}
__device__ __forceinline__ void cpa_commit() {
    asm volatile("cp.async.commit_group;" ::: "memory");
}
template<int N>
__device__ __forceinline__ void cpa_wait() {
    asm volatile("cp.async.wait_group %0;" :: "n"(N) : "memory");
}

// ---------------------------------------------------------------------------
// Split pass: x inputs -> fp16 hi/lo; weights -> fp16 rounded (hi only).
// ---------------------------------------------------------------------------
__global__ void __launch_bounds__(256) split_all(
    const float* __restrict__ q, const float* __restrict__ k, const float* __restrict__ v,
    const float* __restrict__ qkvw, const float* __restrict__ projw)
{
    size_t i4 = (size_t)blockIdx.x * 256 + threadIdx.x;
    const size_t XQ = (size_t)M_ * K_ / 4;          // 1M float4 per x input
    const size_t WQ = (size_t)3 * K_ * K_ / 4;      // qkvw float4 count
    if (i4 < 3 * XQ) {
        size_t sel = i4 / XQ, o = i4 - sel * XQ;
        const float* src = (sel == 0) ? q : ((sel == 1) ? k : v);
        __half* dh = g_xh + sel * (size_t)M_ * K_;
        __half* dl = g_xl + sel * (size_t)M_ * K_;
        float4 x = *((const float4*)src + o);
        unsigned h0, l0, h1, l1;
        splitpk(x.x, x.y, h0, l0);
        splitpk(x.z, x.w, h1, l1);
        *(uint2*)(dh + o * 4) = make_uint2(h0, h1);
        *(uint2*)(dl + o * 4) = make_uint2(l0, l1);
    } else {
        size_t j = i4 - 3 * XQ;
        const float* src; size_t o; __half* dh;
        if (j < WQ) { src = qkvw; o = j; dh = g_wh; }
        else        { src = projw; o = j - WQ; dh = g_wh + (size_t)3 * K_ * K_; }
        float4 x = *((const float4*)src + o);
        *(uint2*)(dh + o * 4) = make_uint2(rnd2(x.x, x.y), rnd2(x.z, x.w));
    }
}

// ---------------------------------------------------------------------------
// fp16x2 GEMM: C[m][n] = sum_k A[m][k]*W[n][k] (+bias); A split hi/lo, W
// rounded. 2 MMAs per logical MMA (Ah*Wh + Al*Wh).
// CTA 128m x 64n, 8 warps, warp tile 32x32. K-chunk 64, cp.async double
// buffered. Buffer 46080 B; 2 buffers = 92160 -> 2 CTAs/SM.
// QKV=1: epilogue rounds to fp16 per-head q/k/v (q scaled 1/8).
// ---------------------------------------------------------------------------
#define GEMM_BUF  46080
#define GEMM_SMEM (2 * GEMM_BUF)

template<int QKV>
__global__ void __launch_bounds__(256, 2) gemm_f16(
    const __half* __restrict__ Ah0, const __half* __restrict__ Al0,
    const __half* __restrict__ Wh,
    const float* __restrict__ bias, float* __restrict__ out)
{
    extern __shared__ __align__(1024) __half smg[];
    const unsigned sb = cvta_s(smg);

    const int tid = threadIdx.x, lane = tid & 31, wid = tid >> 5;
    const int wm = wid & 3, wn = wid >> 2;
    const int m0 = blockIdx.y * 128, n0 = blockIdx.x * 64;

    const __half* Ah = Ah0;
    const __half* Al = Al0;
    int sel = 0;
    if (QKV) {
        sel = n0 >> 10;
        Ah += (size_t)sel * M_ * K_;
        Al += (size_t)sel * M_ * K_;
    }

    int ar[4], as_[4], asg[4];
    #pragma unroll
    for (int i = 0; i < 4; i++) {
        int idx = tid + 256 * i;
        ar[i] = idx >> 3;
        asg[i] = (idx & 7) * 8;
        as_[i] = (idx >> 3) * 144 + (idx & 7) * 16;
    }
    int br[2], bs_[2], bsg[2];
    #pragma unroll
    for (int i = 0; i < 2; i++) {
        int idx = tid + 256 * i;
        br[i] = idx >> 3;
        bsg[i] = (idx & 7) * 8;
        bs_[i] = (idx >> 3) * 144 + (idx & 7) * 16;
    }

    #pragma unroll
    for (int i = 0; i < 4; i++) {
        unsigned d = sb + as_[i];
        size_t g = (size_t)(m0 + ar[i]) * K_ + asg[i];
        cpa16(d,         Ah + g);
        cpa16(d + 18432, Al + g);
    }
    #pragma unroll
    for (int i = 0; i < 2; i++) {
        unsigned d = sb + 36864 + bs_[i];
        cpa16(d, Wh + (size_t)(n0 + br[i]) * K_ + bsg[i]);
    }
    cpa_commit();

    float acc[2][4][4];
    #pragma unroll
    for (int mi = 0; mi < 2; mi++)
        #pragma unroll
        for (int nt = 0; nt < 4; nt++)
            #pragma unroll
            for (int q = 0; q < 4; q++) acc[mi][nt][q] = 0.f;

    const int arow = wm * 32 + (lane & 15);
    const int ak8  = (lane >> 4) * 8;
    const int brow = wn * 32 + (lane >> 4) * 8 + (lane & 7);
    const int bk8  = ((lane >> 3) & 1) * 8;

    const int NC = K_ / 64;
    for (int c = 0; c < NC; c++) {
        if (c + 1 < NC) {
            const unsigned bb = sb + ((c + 1) & 1) * GEMM_BUF;
            const int ko = (c + 1) * 64;
            #pragma unroll
            for (int i = 0; i < 4; i++) {
                unsigned d = bb + as_[i];
                size_t g = (size_t)(m0 + ar[i]) * K_ + ko + asg[i];
                cpa16(d,         Ah + g);
                cpa16(d + 18432, Al + g);
            }
            #pragma unroll
            for (int i = 0; i < 2; i++) {
                unsigned d = bb + 36864 + bs_[i];
                cpa16(d, Wh + (size_t)(n0 + br[i]) * K_ + ko + bsg[i]);
            }
            cpa_commit();
            cpa_wait<1>();
        } else {
            cpa_wait<0>();
        }
        __syncthreads();

        const unsigned ab = sb + (c & 1) * GEMM_BUF;
        #pragma unroll
        for (int ks = 0; ks < 4; ks++) {
            unsigned ah[2][4], al[2][4], bh4[2][4];
            #pragma unroll
            for (int mi = 0; mi < 2; mi++) {
                unsigned off = ab + ((arow + mi * 16) * 72 + ks * 16 + ak8) * 2;
                ldsm4(ah[mi][0], ah[mi][1], ah[mi][2], ah[mi][3], off);
                ldsm4(al[mi][0], al[mi][1], al[mi][2], al[mi][3], off + 18432);
            }
            #pragma unroll
            for (int p = 0; p < 2; p++) {
                unsigned off = ab + 36864 + ((brow + p * 16) * 72 + ks * 16 + bk8) * 2;
                ldsm4(bh4[p][0], bh4[p][1], bh4[p][2], bh4[p][3], off);
            }
            // pass 1: hi*W (8 independent)
            #pragma unroll
            for (int mi = 0; mi < 2; mi++)
                #pragma unroll
                for (int nt = 0; nt < 4; nt++) {
                    int p = nt >> 1, u = (nt & 1) * 2;
                    mma16816(acc[mi][nt], ah[mi][0], ah[mi][1], ah[mi][2], ah[mi][3],
                             bh4[p][u], bh4[p][u + 1]);
                }
            // pass 2: lo*W
            #pragma unroll
            for (int mi = 0; mi < 2; mi++)
                #pragma unroll
                for (int nt = 0; nt < 4; nt++) {
                    int p = nt >> 1, u = (nt & 1) * 2;
                    mma16816(acc[mi][nt], al[mi][0], al[mi][1], al[mi][2], al[mi][3],
                             bh4[p][u], bh4[p][u + 1]);
                }
        }
        __syncthreads();
    }

    // Epilogue
    #pragma unroll
    for (int mi = 0; mi < 2; mi++) {
        const int row = m0 + wm * 32 + mi * 16 + (lane >> 2);
        #pragma unroll
        for (int nt = 0; nt < 4; nt++) {
            const int cg = n0 + wn * 32 + nt * 8 + (lane & 3) * 2;
            float2 bv = *(const float2*)(bias + cg);
            if (QKV) {
                const float scl = (sel == 0) ? 0.125f : 1.0f;
                const int nl = cg - (sel << 10);
                const int h = nl >> 6, d = nl & 63;
                const int bb2 = row >> 11, s = row & (S_ - 1);
                size_t base = ((size_t)((sel * 32 + bb2 * H_ + h) * S_ + s)) * D_ + d;
                *(unsigned*)(g_sh + base) =
                    rnd2((acc[mi][nt][0] + bv.x) * scl, (acc[mi][nt][1] + bv.y) * scl);
                *(unsigned*)(g_sh + base + 8 * D_) =
                    rnd2((acc[mi][nt][2] + bv.x) * scl, (acc[mi][nt][3] + bv.y) * scl);
            } else {
                *(float2*)(out + (size_t)row * E_ + cg) =
                    make_float2(acc[mi][nt][0] + bv.x, acc[mi][nt][1] + bv.y);
                *(float2*)(out + (size_t)(row + 8) * E_ + cg) =
                    make_float2(acc[mi][nt][2] + bv.x, acc[mi][nt][3] + bv.y);
            }
        }
    }
}

// ---------------------------------------------------------------------------
// Flash attention, fp16 mma.sync. BR=64, BC=64, 128 threads, 4 CTAs/SM.
// Q, K, V all rounded fp16. S = Qh*Kh (1 MMA); O += Ph*Vh + Pl*Vh (2 MMAs,
// P split to preserve output accuracy).
// ---------------------------------------------------------------------------
#define FL_BUF  18432
#define FL_SMEM (2 * FL_BUF)

__global__ void __launch_bounds__(128, 4) flash_mma(const float* __restrict__ mask)
{
    extern __shared__ __align__(1024) __half smf[];
    const unsigned sb = cvta_s(smf);

    const int tid = threadIdx.x, lane = tid & 31, wid = tid >> 5;
    const int bh = blockIdx.y;                 // b*H + h
    const int row0 = blockIdx.x * 64;
    const int b = bh >> 4, h = bh & 15;

    const __half* qhb = g_sh + ((size_t)bh * S_ + row0) * D_;
    const __half* khb = g_sh + (size_t)(32 + bh) * S_ * D_;
    const __half* vhb = g_sh + (size_t)(64 + bh) * S_ * D_;

    int kr[4], kso[4], kgf[4];
    #pragma unroll
    for (int i = 0; i < 4; i++) {
        int idx = tid + 128 * i;
        kr[i] = idx >> 3;
        kso[i] = (idx >> 3) * 144 + (idx & 7) * 16;
        kgf[i] = (idx & 7) * 8;
    }

    // group 0: KV t=0 -> buf0 (KH +0, VH +9216)
    #pragma unroll
    for (int i = 0; i < 4; i++) {
        unsigned d = sb + kso[i];
        size_t g = (size_t)kr[i] * D_ + kgf[i];
        cpa16(d,        khb + g);
        cpa16(d + 9216, vhb + g);
    }
    cpa_commit();
    // group 1: Q -> buf1 region
    #pragma unroll
    for (int i = 0; i < 4; i++) {
        unsigned d = sb + FL_BUF + kso[i];
        cpa16(d, qhb + (size_t)kr[i] * D_ + kgf[i]);
    }
    cpa_commit();
    cpa_wait<0>();
    __syncthreads();

    unsigned qh[4][4];
    {
        const int qrow = wid * 16 + (lane & 15);
        const int qk8 = (lane >> 4) * 8;
        #pragma unroll
        for (int ks = 0; ks < 4; ks++) {
            unsigned off = sb + FL_BUF + (qrow * 72 + ks * 16 + qk8) * 2;
            ldsm4(qh[ks][0], qh[ks][1], qh[ks][2], qh[ks][3], off);
        }
    }
    __syncthreads();   // Q reads done before t=1 prefetch overwrites buf1

    float O[8][4];
    #pragma unroll
    for (int nt = 0; nt < 8; nt++)
        #pragma unroll
        for (int q = 0; q < 4; q++) O[nt][q] = 0.f;
    float mr0 = -1e30f, mr1 = -1e30f, lr0 = 0.f, lr1 = 0.f;

    const int krow = (lane >> 4) * 8 + (lane & 7);       // + p*16
    const int kk8  = ((lane >> 3) & 1) * 8;
    const int vrow = ((lane >> 3) & 1) * 8 + (lane & 7); // + ks*16
    const int vc8  = (lane >> 4) * 8;                    // + p*16

    const int r1 = row0 + wid * 16 + (lane >> 2);
    const float* mrow1 = mask + (size_t)r1 * S_;
    const float* mrow2 = mrow1 + 8 * S_;

    const int NT = S_ / 64;   // 32
    for (int t = 0; t < NT; t++) {
        // hoisted mask loads
        const int cb = t * 64 + (lane & 3) * 2;
        float2 mk1[8], mk2[8];
        #pragma unroll
        for (int nt = 0; nt < 8; nt++) {
            mk1[nt] = *(const float2*)(mrow1 + cb + nt * 8);
            mk2[nt] = *(const float2*)(mrow2 + cb + nt * 8);
        }

        if (t + 1 < NT) {
            const unsigned bb = sb + ((t + 1) & 1) * FL_BUF;
            #pragma unroll
            for (int i = 0; i < 4; i++) {
                unsigned d = bb + kso[i];
                size_t g = (size_t)((t + 1) * 64 + kr[i]) * D_ + kgf[i];
                cpa16(d,        khb + g);
                cpa16(d + 9216, vhb + g);
            }
            cpa_commit();
            cpa_wait<1>();
        } else {
            cpa_wait<0>();
        }
        __syncthreads();

        const unsigned kbb = sb + (t & 1) * FL_BUF;
        const unsigned vbb = kbb + 9216;

        // ---- S = Qh K (single MMA pass) ----
        float sa[8][4];
        #pragma unroll
        for (int nt = 0; nt < 8; nt++)
            #pragma unroll
            for (int q = 0; q < 4; q++) sa[nt][q] = 0.f;

        #pragma unroll
        for (int ks = 0; ks < 4; ks++) {
            unsigned bh4[4][4];
            #pragma unroll
            for (int p = 0; p < 4; p++) {
                unsigned off = kbb + ((krow + p * 16) * 72 + ks * 16 + kk8) * 2;
                ldsm4(bh4[p][0], bh4[p][1], bh4[p][2], bh4[p][3], off);
            }
            #pragma unroll
            for (int nt = 0; nt < 8; nt++) {
                int p = nt >> 1, u = (nt & 1) * 2;
                mma16816(sa[nt], qh[ks][0], qh[ks][1], qh[ks][2], qh[ks][3],
                         bh4[p][u], bh4[p][u + 1]);
            }
        }

        // ---- mask + online softmax (warp-local) ----
        float mx0 = -1e30f, mx1 = -1e30f;
        #pragma unroll
        for (int nt = 0; nt < 8; nt++) {
            sa[nt][0] += mk1[nt].x; sa[nt][1] += mk1[nt].y;
            sa[nt][2] += mk2[nt].x; sa[nt][3] += mk2[nt].y;
            mx0 = fmaxf(mx0, fmaxf(sa[nt][0], sa[nt][1]));
            mx1 = fmaxf(mx1, fmaxf(sa[nt][2], sa[nt][3]));
        }
        mx0 = fmaxf(mx0, __shfl_xor_sync(0xffffffffu, mx0, 1));
        mx0 = fmaxf(mx0, __shfl_xor_sync(0xffffffffu, mx0, 2));
        mx1 = fmaxf(mx1, __shfl_xor_sync(0xffffffffu, mx1, 1));
        mx1 = fmaxf(mx1, __shfl_xor_sync(0xffffffffu, mx1, 2));

        float mn0 = fmaxf(mr0, mx0), mn1 = fmaxf(mr1, mx1);
        float a0 = __expf(mr0 - mn0), a1 = __expf(mr1 - mn1);
        mr0 = mn0; mr1 = mn1;

        float s0 = 0.f, s1 = 0.f;
        #pragma unroll
        for (int nt = 0; nt < 8; nt++) {
            sa[nt][0] = __expf(sa[nt][0] - mn0); s0 += sa[nt][0];
            sa[nt][1] = __expf(sa[nt][1] - mn0); s0 += sa[nt][1];
            sa[nt][2] = __expf(sa[nt][2] - mn1); s1 += sa[nt][2];
            sa[nt][3] = __expf(sa[nt][3] - mn1); s1 += sa[nt][3];
        }
        s0 += __shfl_xor_sync(0xffffffffu, s0, 1);
        s0 += __shfl_xor_sync(0xffffffffu, s0, 2);
        s1 += __shfl_xor_sync(0xffffffffu, s1, 1);
        s1 += __shfl_xor_sync(0xffffffffu, s1, 2);
        lr0 = lr0 * a0 + s0;
        lr1 = lr1 * a1 + s1;
        #pragma unroll
        for (int nt = 0; nt < 8; nt++) {
            O[nt][0] *= a0; O[nt][1] *= a0;
            O[nt][2] *= a1; O[nt][3] *= a1;
        }

        // ---- O += Ph V + Pl V ----
        #pragma unroll
        for (int ks = 0; ks < 4; ks++) {
            int j0 = 2 * ks, j1 = j0 + 1;
            unsigned ph0, ph1, ph2, ph3, pl0, pl1, pl2, pl3;
            splitpk(sa[j0][0], sa[j0][1], ph0, pl0);
            splitpk(sa[j0][2], sa[j0][3], ph1, pl1);
            splitpk(sa[j1][0], sa[j1][1], ph2, pl2);
            splitpk(sa[j1][2], sa[j1][3], ph3, pl3);
            unsigned vh4[4][4];
            #pragma unroll
            for (int p = 0; p < 4; p++) {
                unsigned off = vbb + ((vrow + ks * 16) * 72 + vc8 + p * 16) * 2;
                ldsm4t(vh4[p][0], vh4[p][1], vh4[p][2], vh4[p][3], off);
            }
            #pragma unroll
            for (int nt = 0; nt < 8; nt++) {
                int p = nt >> 1, u = (nt & 1) * 2;
                mma16816(O[nt], ph0, ph1, ph2, ph3, vh4[p][u], vh4[p][u + 1]);
            }
            #pragma unroll
            for (int nt = 0; nt < 8; nt++) {
                int p = nt >> 1, u = (nt & 1) * 2;
                mma16816(O[nt], pl0, pl1, pl2, pl3, vh4[p][u], vh4[p][u + 1]);
            }
        }
        __syncthreads();
    }

    // ---- Epilogue: normalize, split, write ctx hi/lo ----
    float i0 = 1.f / lr0, i1 = 1.f / lr1;
    size_t o1 = ((size_t)(b * S_ + r1)) * E_ + h * D_ + (lane & 3) * 2;
    size_t o2 = o1 + (size_t)8 * E_;
    #pragma unroll
    for (int nt = 0; nt < 8; nt++) {
        unsigned hw, lw;
        splitpk(O[nt][0] * i0, O[nt][1] * i0, hw, lw);
        *(unsigned*)(g_ch + o1 + nt * 8) = hw;
        *(unsigned*)(g_cl + o1 + nt * 8) = lw;
        splitpk(O[nt][2] * i1, O[nt][3] * i1, hw, lw);
        *(unsigned*)(g_ch + o2 + nt * 8) = hw;
        *(unsigned*)(g_cl + o2 + nt * 8) = lw;
    }
}

// ---------------------------------------------------------------------------
// Launch: split pass -> QKV GEMM -> flash -> output GEMM.
// ---------------------------------------------------------------------------
extern "C" void kernel_launch(void* const* d_in, const int* in_sizes, int n_in,
                              void* d_out, int out_size)
{
    const float* query = (const float*)d_in[0];
    const float* key   = (const float*)d_in[1];
    const float* value = (const float*)d_in[2];
    const float* qkvw  = (const float*)d_in[3];
    const float* qkvb  = (const float*)d_in[4];
    const float* projw = (const float*)d_in[5];
    const float* projb = (const float*)d_in[6];
    const float* mask  = (const float*)d_in[7];

    __half *xh, *xl, *wh, *ch, *cl;
    cudaGetSymbolAddress((void**)&xh, g_xh);
    cudaGetSymbolAddress((void**)&xl, g_xl);
    cudaGetSymbolAddress((void**)&wh, g_wh);
    cudaGetSymbolAddress((void**)&ch, g_ch);
    cudaGetSymbolAddress((void**)&cl, g_cl);

    cudaFuncSetAttribute(gemm_f16<1>, cudaFuncAttributeMaxDynamicSharedMemorySize, GEMM_SMEM);
    cudaFuncSetAttribute(gemm_f16<0>, cudaFuncAttributeMaxDynamicSharedMemorySize, GEMM_SMEM);
    cudaFuncSetAttribute(flash_mma, cudaFuncAttributeMaxDynamicSharedMemorySize, FL_SMEM);

    // 1. split inputs (hi/lo) + weights (rounded)
    split_all<<<16384, 256>>>(query, key, value, qkvw, projw);

    // 2. fused QKV projection -> per-head q/k/v (rounded fp16)
    gemm_f16<1><<<dim3(48, 32), 256, GEMM_SMEM>>>(xh, xl, wh, qkvb, nullptr);

    // 3. flash attention -> split ctx
    flash_mma<<<dim3(S_ / 64, B_ * H_), 128, FL_SMEM>>>(mask);

    // 4. output projection -> fp32 d_out (16 blocks cover n in [0,1024))
    gemm_f16<0><<<dim3(16, 32), 256, GEMM_SMEM>>>(ch, cl,
                                                  wh + (size_t)3 * K_ * K_,
                                                  projb, (float*)d_out);
}

// round 15
// speedup vs baseline: 1.8242x; 1.2361x over previous
#include <cuda_runtime.h>
#include <cuda_fp16.h>

#define B_ 2
#define S_ 2048
#define E_ 1024
#define H_ 16
#define D_ 64
#define M_ 4096
#define K_ 1024

// ---------------------------------------------------------------------------
// Scratch (__device__ globals). Everything single rounded fp16 now except
// the P fragments inside flash (split hi/lo at use site).
// ---------------------------------------------------------------------------
__device__ __align__(256) __half g_x[(size_t)3*M_*K_];    // rounded q/k/v inputs
__device__ __align__(256) __half g_w[(size_t)4*K_*K_];    // rounded qkvw + projw
__device__ __align__(256) __half g_s[(size_t)3*B_*H_*S_*D_]; // rounded q/k/v heads
__device__ __align__(256) __half g_c[(size_t)M_*E_];      // rounded ctx

// ---------------------------------------------------------------------------
// Helpers
// ---------------------------------------------------------------------------
__device__ __forceinline__ unsigned cvta_s(const void* p) {
    return (unsigned)__cvta_generic_to_shared(p);
}
__device__ __forceinline__ unsigned pkh2(__half a, __half b) {
    return (unsigned)__half_as_ushort(a) | ((unsigned)__half_as_ushort(b) << 16);
}
__device__ __forceinline__ void splitpk(float x, float y, unsigned& h, unsigned& l) {
    __half hx = __float2half_rn(x);
    __half hy = __float2half_rn(y);
    float rx = x - __half2float(hx);
    float ry = y - __half2float(hy);
    h = pkh2(hx, hy);
    l = pkh2(__float2half_rn(rx), __float2half_rn(ry));
}
__device__ __forceinline__ unsigned rnd2(float x, float y) {
    return pkh2(__float2half_rn(x), __float2half_rn(y));
}
__device__ __forceinline__ void ldsm4(unsigned& r0, unsigned& r1, unsigned& r2, unsigned& r3,
                                      unsigned a) {
    asm volatile("ldmatrix.sync.aligned.m8n8.x4.shared.b16 {%0,%1,%2,%3}, [%4];"
                 : "=r"(r0), "=r"(r1), "=r"(r2), "=r"(r3) : "r"(a));
}
__device__ __forceinline__ void ldsm4t(unsigned& r0, unsigned& r1, unsigned& r2, unsigned& r3,
                                       unsigned a) {
    asm volatile("ldmatrix.sync.aligned.m8n8.x4.trans.shared.b16 {%0,%1,%2,%3}, [%4];"
                 : "=r"(r0), "=r"(r1), "=r"(r2), "=r"(r3) : "r"(a));
}
// fp16 operands, fp32 accumulator. Non-volatile (pure register op).
__device__ __forceinline__ void mma16816(float* c,
                                         unsigned a0, unsigned a1, unsigned a2, unsigned a3,
                                         unsigned b0, unsigned b1) {
    asm("mma.sync.aligned.m16n8k16.row.col.f32.f16.f16.f32 "
        "{%0,%1,%2,%3}, {%4,%5,%6,%7}, {%8,%9}, {%0,%1,%2,%3};"
        : "+f"(c[0]), "+f"(c[1]), "+f"(c[2]), "+f"(c[3])
        : "r"(a0), "r"(a1), "r"(a2), "r"(a3), "r"(b0), "r"(b1));
}
__device__ __forceinline__ void cpa16(unsigned dst, const void* src) {
    asm volatile("cp.async.cg.shared.global [%0], [%1], 16;" :: "r"(dst), "l"(src));
}
__device__ __forceinline__ void cpa_commit() {
    asm volatile("cp.async.commit_group;" ::: "memory");
}
template<int N>
__device__ __forceinline__ void cpa_wait() {
    asm volatile("cp.async.wait_group %0;" :: "n"(N) : "memory");
}

// ---------------------------------------------------------------------------
// Round pass: all fp32 inputs + weights -> fp16. 4M float4.
// ---------------------------------------------------------------------------
__global__ void __launch_bounds__(256) round_all(
    const float* __restrict__ q, const float* __restrict__ k, const float* __restrict__ v,
    const float* __restrict__ qkvw, const float* __restrict__ projw)
{
    size_t i4 = (size_t)blockIdx.x * 256 + threadIdx.x;
    const size_t XQ = (size_t)M_ * K_ / 4;
    const size_t WQ = (size_t)3 * K_ * K_ / 4;
    const float* src; __half* dh; size_t o;
    if (i4 < 3 * XQ) {
        size_t sel = i4 / XQ; o = i4 - sel * XQ;
        src = (sel == 0) ? q : ((sel == 1) ? k : v);
        dh = g_x + sel * (size_t)M_ * K_;
    } else {
        size_t j = i4 - 3 * XQ;
        if (j < WQ) { src = qkvw; o = j; dh = g_w; }
        else        { src = projw; o = j - WQ; dh = g_w + (size_t)3 * K_ * K_; }
    }
    float4 x = *((const float4*)src + o);
    *(uint2*)(dh + o * 4) = make_uint2(rnd2(x.x, x.y), rnd2(x.z, x.w));
}

// ---------------------------------------------------------------------------
// Plain fp16 GEMM (fp32 accum): C[m][n] = sum_k A[m][k]*W[n][k] (+bias).
// CTA 128m x 64n, 8 warps, warp tile 32x32, 1 MMA per logical MMA.
// K-chunk 64, cp.async double buffered: buffer = A 18432 + W 9216 = 27648 B.
// QKV=1: A selected by n0>>10; epilogue rounds per-head q/k/v (q * 1/8).
// QKV=0: fp32 out + bias.
// ---------------------------------------------------------------------------
#define GEMM_BUF  27648
#define GEMM_SMEM (2 * GEMM_BUF)

template<int QKV>
__global__ void __launch_bounds__(256, 2) gemm_f16(
    const __half* __restrict__ A0, const __half* __restrict__ W,
    const float* __restrict__ bias, float* __restrict__ out)
{
    extern __shared__ __align__(1024) __half smg[];
    const unsigned sb = cvta_s(smg);

    const int tid = threadIdx.x, lane = tid & 31, wid = tid >> 5;
    const int wm = wid & 3, wn = wid >> 2;
    const int m0 = blockIdx.y * 128, n0 = blockIdx.x * 64;

    const __half* A = A0;
    int sel = 0;
    if (QKV) {
        sel = n0 >> 10;
        A += (size_t)sel * M_ * K_;
    }

    int ar[4], as_[4], asg[4];
    #pragma unroll
    for (int i = 0; i < 4; i++) {
        int idx = tid + 256 * i;
        ar[i] = idx >> 3;
        asg[i] = (idx & 7) * 8;
        as_[i] = (idx >> 3) * 144 + (idx & 7) * 16;
    }
    int br[2], bs_[2], bsg[2];
    #pragma unroll
    for (int i = 0; i < 2; i++) {
        int idx = tid + 256 * i;
        br[i] = idx >> 3;
        bsg[i] = (idx & 7) * 8;
        bs_[i] = (idx >> 3) * 144 + (idx & 7) * 16;
    }

    #pragma unroll
    for (int i = 0; i < 4; i++)
        cpa16(sb + as_[i], A + (size_t)(m0 + ar[i]) * K_ + asg[i]);
    #pragma unroll
    for (int i = 0; i < 2; i++)
        cpa16(sb + 18432 + bs_[i], W + (size_t)(n0 + br[i]) * K_ + bsg[i]);
    cpa_commit();

    float acc[2][4][4];
    #pragma unroll
    for (int mi = 0; mi < 2; mi++)
        #pragma unroll
        for (int nt = 0; nt < 4; nt++)
            #pragma unroll
            for (int q = 0; q < 4; q++) acc[mi][nt][q] = 0.f;

    const int arow = wm * 32 + (lane & 15);
    const int ak8  = (lane >> 4) * 8;
    const int brow = wn * 32 + (lane >> 4) * 8 + (lane & 7);
    const int bk8  = ((lane >> 3) & 1) * 8;

    const int NC = K_ / 64;
    for (int c = 0; c < NC; c++) {
        if (c + 1 < NC) {
            const unsigned bb = sb + ((c + 1) & 1) * GEMM_BUF;
            const int ko = (c + 1) * 64;
            #pragma unroll
            for (int i = 0; i < 4; i++)
                cpa16(bb + as_[i], A + (size_t)(m0 + ar[i]) * K_ + ko + asg[i]);
            #pragma unroll
            for (int i = 0; i < 2; i++)
                cpa16(bb + 18432 + bs_[i], W + (size_t)(n0 + br[i]) * K_ + ko + bsg[i]);
            cpa_commit();
            cpa_wait<1>();
        } else {
            cpa_wait<0>();
        }
        __syncthreads();

        const unsigned ab = sb + (c & 1) * GEMM_BUF;
        #pragma unroll
        for (int ks = 0; ks < 4; ks++) {
            unsigned ah[2][4], bh4[2][4];
            #pragma unroll
            for (int mi = 0; mi < 2; mi++) {
                unsigned off = ab + ((arow + mi * 16) * 72 + ks * 16 + ak8) * 2;
                ldsm4(ah[mi][0], ah[mi][1], ah[mi][2], ah[mi][3], off);
            }
            #pragma unroll
            for (int p = 0; p < 2; p++) {
                unsigned off = ab + 18432 + ((brow + p * 16) * 72 + ks * 16 + bk8) * 2;
                ldsm4(bh4[p][0], bh4[p][1], bh4[p][2], bh4[p][3], off);
            }
            #pragma unroll
            for (int mi = 0; mi < 2; mi++)
                #pragma unroll
                for (int nt = 0; nt < 4; nt++) {
                    int p = nt >> 1, u = (nt & 1) * 2;
                    mma16816(acc[mi][nt], ah[mi][0], ah[mi][1], ah[mi][2], ah[mi][3],
                             bh4[p][u], bh4[p][u + 1]);
                }
        }
        __syncthreads();
    }

    // Epilogue
    #pragma unroll
    for (int mi = 0; mi < 2; mi++) {
        const int row = m0 + wm * 32 + mi * 16 + (lane >> 2);
        #pragma unroll
        for (int nt = 0; nt < 4; nt++) {
            const int cg = n0 + wn * 32 + nt * 8 + (lane & 3) * 2;
            float2 bv = *(const float2*)(bias + cg);
            if (QKV) {
                const float scl = (sel == 0) ? 0.125f : 1.0f;
                const int nl = cg - (sel << 10);
                const int h = nl >> 6, d = nl & 63;
                const int bb2 = row >> 11, s = row & (S_ - 1);
                size_t base = ((size_t)((sel * 32 + bb2 * H_ + h) * S_ + s)) * D_ + d;
                *(unsigned*)(g_s + base) =
                    rnd2((acc[mi][nt][0] + bv.x) * scl, (acc[mi][nt][1] + bv.y) * scl);
                *(unsigned*)(g_s + base + 8 * D_) =
                    rnd2((acc[mi][nt][2] + bv.x) * scl, (acc[mi][nt][3] + bv.y) * scl);
            } else {
                *(float2*)(out + (size_t)row * E_ + cg) =
                    make_float2(acc[mi][nt][0] + bv.x, acc[mi][nt][1] + bv.y);
                *(float2*)(out + (size_t)(row + 8) * E_ + cg) =
                    make_float2(acc[mi][nt][2] + bv.x, acc[mi][nt][3] + bv.y);
            }
        }
    }
}

// ---------------------------------------------------------------------------
// Flash attention, fp16 mma.sync. BR=64, BC=64, 128 threads, 4 CTAs/SM.
// S = Q*K (1 MMA pass); O += Ph*V + Pl*V (P split preserved for accuracy).
// Epilogue rounds ctx to fp16 (single array).
// ---------------------------------------------------------------------------
#define FL_BUF  18432
#define FL_SMEM (2 * FL_BUF)

__global__ void __launch_bounds__(128, 4) flash_mma(const float* __restrict__ mask)
{
    extern __shared__ __align__(1024) __half smf[];
    const unsigned sb = cvta_s(smf);

    const int tid = threadIdx.x, lane = tid & 31, wid = tid >> 5;
    const int bh = blockIdx.y;                 // b*H + h
    const int row0 = blockIdx.x * 64;
    const int b = bh >> 4, h = bh & 15;

    const __half* qhb = g_s + ((size_t)bh * S_ + row0) * D_;
    const __half* khb = g_s + (size_t)(32 + bh) * S_ * D_;
    const __half* vhb = g_s + (size_t)(64 + bh) * S_ * D_;

    int kr[4], kso[4], kgf[4];
    #pragma unroll
    for (int i = 0; i < 4; i++) {
        int idx = tid + 128 * i;
        kr[i] = idx >> 3;
        kso[i] = (idx >> 3) * 144 + (idx & 7) * 16;
        kgf[i] = (idx & 7) * 8;
    }

    // group 0: KV t=0 -> buf0 (KH +0, VH +9216)
    #pragma unroll
    for (int i = 0; i < 4; i++) {
        unsigned d = sb + kso[i];
        size_t g = (size_t)kr[i] * D_ + kgf[i];
        cpa16(d,        khb + g);
        cpa16(d + 9216, vhb + g);
    }
    cpa_commit();
    // group 1: Q -> buf1 region
    #pragma unroll
    for (int i = 0; i < 4; i++) {
        unsigned d = sb + FL_BUF + kso[i];
        cpa16(d, qhb + (size_t)kr[i] * D_ + kgf[i]);
    }
    cpa_commit();
    cpa_wait<0>();
    __syncthreads();

    unsigned qh[4][4];
    {
        const int qrow = wid * 16 + (lane & 15);
        const int qk8 = (lane >> 4) * 8;
        #pragma unroll
        for (int ks = 0; ks < 4; ks++) {
            unsigned off = sb + FL_BUF + (qrow * 72 + ks * 16 + qk8) * 2;
            ldsm4(qh[ks][0], qh[ks][1], qh[ks][2], qh[ks][3], off);
        }
    }
    __syncthreads();   // Q reads done before t=1 prefetch overwrites buf1

    float O[8][4];
    #pragma unroll
    for (int nt = 0; nt < 8; nt++)
        #pragma unroll
        for (int q = 0; q < 4; q++) O[nt][q] = 0.f;
    float mr0 = -1e30f, mr1 = -1e30f, lr0 = 0.f, lr1 = 0.f;

    const int krow = (lane >> 4) * 8 + (lane & 7);       // + p*16
    const int kk8  = ((lane >> 3) & 1) * 8;
    const int vrow = ((lane >> 3) & 1) * 8 + (lane & 7); // + ks*16
    const int vc8  = (lane >> 4) * 8;                    // + p*16

    const int r1 = row0 + wid * 16 + (lane >> 2);
    const float* mrow1 = mask + (size_t)r1 * S_;
    const float* mrow2 = mrow1 + 8 * S_;

    const int NT = S_ / 64;   // 32
    for (int t = 0; t < NT; t++) {
        // hoisted mask loads
        const int cb = t * 64 + (lane & 3) * 2;
        float2 mk1[8], mk2[8];
        #pragma unroll
        for (int nt = 0; nt < 8; nt++) {
            mk1[nt] = *(const float2*)(mrow1 + cb + nt * 8);
            mk2[nt] = *(const float2*)(mrow2 + cb + nt * 8);
        }

        if (t + 1 < NT) {
            const unsigned bb = sb + ((t + 1) & 1) * FL_BUF;
            #pragma unroll
            for (int i = 0; i < 4; i++) {
                unsigned d = bb + kso[i];
                size_t g = (size_t)((t + 1) * 64 + kr[i]) * D_ + kgf[i];
                cpa16(d,        khb + g);
                cpa16(d + 9216, vhb + g);
            }
            cpa_commit();
            cpa_wait<1>();
        } else {
            cpa_wait<0>();
        }
        __syncthreads();

        const unsigned kbb = sb + (t & 1) * FL_BUF;
        const unsigned vbb = kbb + 9216;

        // ---- S = Q K (single MMA pass) ----
        float sa[8][4];
        #pragma unroll
        for (int nt = 0; nt < 8; nt++)
            #pragma unroll
            for (int q = 0; q < 4; q++) sa[nt][q] = 0.f;

        #pragma unroll
        for (int ks = 0; ks < 4; ks++) {
            unsigned bh4[4][4];
            #pragma unroll
            for (int p = 0; p < 4; p++) {
                unsigned off = kbb + ((krow + p * 16) * 72 + ks * 16 + kk8) * 2;
                ldsm4(bh4[p][0], bh4[p][1], bh4[p][2], bh4[p][3], off);
            }
            #pragma unroll
            for (int nt = 0; nt < 8; nt++) {
                int p = nt >> 1, u = (nt & 1) * 2;
                mma16816(sa[nt], qh[ks][0], qh[ks][1], qh[ks][2], qh[ks][3],
                         bh4[p][u], bh4[p][u + 1]);
            }
        }

        // ---- mask + online softmax (warp-local) ----
        float mx0 = -1e30f, mx1 = -1e30f;
        #pragma unroll
        for (int nt = 0; nt < 8; nt++) {
            sa[nt][0] += mk1[nt].x; sa[nt][1] += mk1[nt].y;
            sa[nt][2] += mk2[nt].x; sa[nt][3] += mk2[nt].y;
            mx0 = fmaxf(mx0, fmaxf(sa[nt][0], sa[nt][1]));
            mx1 = fmaxf(mx1, fmaxf(sa[nt][2], sa[nt][3]));
        }
        mx0 = fmaxf(mx0, __shfl_xor_sync(0xffffffffu, mx0, 1));
        mx0 = fmaxf(mx0, __shfl_xor_sync(0xffffffffu, mx0, 2));
        mx1 = fmaxf(mx1, __shfl_xor_sync(0xffffffffu, mx1, 1));
        mx1 = fmaxf(mx1, __shfl_xor_sync(0xffffffffu, mx1, 2));

        float mn0 = fmaxf(mr0, mx0), mn1 = fmaxf(mr1, mx1);
        float a0 = __expf(mr0 - mn0), a1 = __expf(mr1 - mn1);
        mr0 = mn0; mr1 = mn1;

        float s0 = 0.f, s1 = 0.f;
        #pragma unroll
        for (int nt = 0; nt < 8; nt++) {
            sa[nt][0] = __expf(sa[nt][0] - mn0); s0 += sa[nt][0];
            sa[nt][1] = __expf(sa[nt][1] - mn0); s0 += sa[nt][1];
            sa[nt][2] = __expf(sa[nt][2] - mn1); s1 += sa[nt][2];
            sa[nt][3] = __expf(sa[nt][3] - mn1); s1 += sa[nt][3];
        }
        s0 += __shfl_xor_sync(0xffffffffu, s0, 1);
        s0 += __shfl_xor_sync(0xffffffffu, s0, 2);
        s1 += __shfl_xor_sync(0xffffffffu, s1, 1);
        s1 += __shfl_xor_sync(0xffffffffu, s1, 2);
        lr0 = lr0 * a0 + s0;
        lr1 = lr1 * a1 + s1;
        #pragma unroll
        for (int nt = 0; nt < 8; nt++) {
            O[nt][0] *= a0; O[nt][1] *= a0;
            O[nt][2] *= a1; O[nt][3] *= a1;
        }

        // ---- O += Ph V + Pl V ----
        #pragma unroll
        for (int ks = 0; ks < 4; ks++) {
            int j0 = 2 * ks, j1 = j0 + 1;
            unsigned ph0, ph1, ph2, ph3, pl0, pl1, pl2, pl3;
            splitpk(sa[j0][0], sa[j0][1], ph0, pl0);
            splitpk(sa[j0][2], sa[j0][3], ph1, pl1);
            splitpk(sa[j1][0], sa[j1][1], ph2, pl2);
            splitpk(sa[j1][2], sa[j1][3], ph3, pl3);
            unsigned vh4[4][4];
            #pragma unroll
            for (int p = 0; p < 4; p++) {
                unsigned off = vbb + ((vrow + ks * 16) * 72 + vc8 + p * 16) * 2;
                ldsm4t(vh4[p][0], vh4[p][1], vh4[p][2], vh4[p][3], off);
            }
            #pragma unroll
            for (int nt = 0; nt < 8; nt++) {
                int p = nt >> 1, u = (nt & 1) * 2;
                mma16816(O[nt], ph0, ph1, ph2, ph3, vh4[p][u], vh4[p][u + 1]);
            }
            #pragma unroll
            for (int nt = 0; nt < 8; nt++) {
                int p = nt >> 1, u = (nt & 1) * 2;
                mma16816(O[nt], pl0, pl1, pl2, pl3, vh4[p][u], vh4[p][u + 1]);
            }
        }
        __syncthreads();
    }

    // ---- Epilogue: normalize, round, write ctx fp16 ----
    float i0 = 1.f / lr0, i1 = 1.f / lr1;
    size_t o1 = ((size_t)(b * S_ + r1)) * E_ + h * D_ + (lane & 3) * 2;
    size_t o2 = o1 + (size_t)8 * E_;
    #pragma unroll
    for (int nt = 0; nt < 8; nt++) {
        *(unsigned*)(g_c + o1 + nt * 8) = rnd2(O[nt][0] * i0, O[nt][1] * i0);
        *(unsigned*)(g_c + o2 + nt * 8) = rnd2(O[nt][2] * i1, O[nt][3] * i1);
    }
}

// ---------------------------------------------------------------------------
// Launch: round pass -> QKV GEMM -> flash -> output GEMM.
// ---------------------------------------------------------------------------
extern "C" void kernel_launch(void* const* d_in, const int* in_sizes, int n_in,
                              void* d_out, int out_size)
{
    const float* query = (const float*)d_in[0];
    const float* key   = (const float*)d_in[1];
    const float* value = (const float*)d_in[2];
    const float* qkvw  = (const float*)d_in[3];
    const float* qkvb  = (const float*)d_in[4];
    const float* projw = (const float*)d_in[5];
    const float* projb = (const float*)d_in[6];
    const float* mask  = (const float*)d_in[7];

    __half *x, *w, *c;
    cudaGetSymbolAddress((void**)&x, g_x);
    cudaGetSymbolAddress((void**)&w, g_w);
    cudaGetSymbolAddress((void**)&c, g_c);

    cudaFuncSetAttribute(gemm_f16<1>, cudaFuncAttributeMaxDynamicSharedMemorySize, GEMM_SMEM);
    cudaFuncSetAttribute(gemm_f16<0>, cudaFuncAttributeMaxDynamicSharedMemorySize, GEMM_SMEM);
    cudaFuncSetAttribute(flash_mma, cudaFuncAttributeMaxDynamicSharedMemorySize, FL_SMEM);

    // 1. round inputs + weights to fp16
    round_all<<<16384, 256>>>(query, key, value, qkvw, projw);

    // 2. fused QKV projection -> per-head q/k/v (rounded fp16)
    gemm_f16<1><<<dim3(48, 32), 256, GEMM_SMEM>>>(x, w, qkvb, nullptr);

    // 3. flash attention -> rounded ctx
    flash_mma<<<dim3(S_ / 64, B_ * H_), 128, FL_SMEM>>>(mask);

    // 4. output projection -> fp32 d_out (16 blocks cover n in [0,1024))
    gemm_f16<0><<<dim3(16, 32), 256, GEMM_SMEM>>>(c, w + (size_t)3 * K_ * K_,
                                                  projb, (float*)d_out);
}